// round 1
// baseline (speedup 1.0000x reference)
#include <cuda_runtime.h>
#include <math.h>

#define GN   4096
#define FIN  512
#define FH   128
#define NH   4
#define FOUT 64
#define ALPHA 0.2f

// ---------------- scratch (device globals; no allocations allowed) ----------
__device__ float    g_h1[NH * GN * FH];        // [h][n][f]  8 MB
__device__ float    g_src1[NH * GN];
__device__ float    g_dst1[NH * GN];
__device__ float    g_src2[GN];
__device__ float    g_dst2[GN];
__device__ float    g_mdst[NH + 1];            // per-head max_j dst (layer1: 0..3, layer2: 4)
__device__ unsigned g_adj[GN * GN / 32];       // bit mask, 2 MB (L2 resident)
__device__ float    g_x2[GN * (NH * FH)];      // layer-1 output, concat layout, 8 MB
__device__ float    g_h2[GN * FOUT];           // 1 MB

// ---------------- adjacency pack: int32 -> bit mask -------------------------
__global__ void pack_adj_kernel(const int* __restrict__ adj) {
    int i = blockIdx.x * blockDim.x + threadIdx.x;       // element index over N*N
    unsigned bal = __ballot_sync(0xffffffffu, adj[i] > 0);
    if ((threadIdx.x & 31) == 0) g_adj[i >> 5] = bal;
}

// ---------------- GEMM: C[M,NC] = A[M,K] @ B[K,NC] (per-head via blockIdx.z)
// LAYER==1: A=features, B=W1+z*K*NC, C=g_h1+z*N*NC.  LAYER==2: A=g_x2, B=W2, C=g_h2.
template<int K, int NC, int LAYER>
__global__ __launch_bounds__(256) void gemm_kernel(const float* __restrict__ Aarg,
                                                   const float* __restrict__ Wall) {
    constexpr int BM = 64, BK = 16;
    const float* A = (LAYER == 1) ? Aarg : g_x2;
    const float* B = Wall + (size_t)blockIdx.z * K * NC;
    float*       C = (LAYER == 1) ? (g_h1 + (size_t)blockIdx.z * GN * NC) : g_h2;
    const int r0 = blockIdx.x * BM;
    const int c0 = blockIdx.y * 64;

    __shared__ float a_s[BK][BM + 1];   // transposed A tile
    __shared__ float b_s[BK][64];

    const int tid = threadIdx.x;
    const int tx = tid & 15, ty = tid >> 4;   // 16x16 threads, 4x4 microtile

    unsigned long long acc[4][2] = {};

    for (int k0 = 0; k0 < K; k0 += BK) {
        __syncthreads();
        {   // load A tile 64x16 (float4), store transposed
            int ar = tid >> 2;
            int ak = (tid & 3) * 4;
            float4 v = *(const float4*)&A[(size_t)(r0 + ar) * K + k0 + ak];
            a_s[ak + 0][ar] = v.x; a_s[ak + 1][ar] = v.y;
            a_s[ak + 2][ar] = v.z; a_s[ak + 3][ar] = v.w;
        }
        {   // load B tile 16x64 (float4)
            int bk = tid >> 4;
            int bc = (tid & 15) * 4;
            *(float4*)&b_s[bk][bc] = *(const float4*)&B[(size_t)(k0 + bk) * NC + c0 + bc];
        }
        __syncthreads();
        #pragma unroll
        for (int kk = 0; kk < BK; kk++) {
            ulonglong2 bv = *(const ulonglong2*)&b_s[kk][tx * 4];
            #pragma unroll
            for (int i = 0; i < 4; i++) {
                float av = a_s[kk][ty * 4 + i];
                unsigned long long ap;
                asm("mov.b64 %0, {%1, %1};" : "=l"(ap) : "f"(av));
                asm("fma.rn.f32x2 %0, %1, %2, %0;" : "+l"(acc[i][0]) : "l"(ap), "l"(bv.x));
                asm("fma.rn.f32x2 %0, %1, %2, %0;" : "+l"(acc[i][1]) : "l"(ap), "l"(bv.y));
            }
        }
    }
    #pragma unroll
    for (int i = 0; i < 4; i++) {
        float4 o;
        asm("mov.b64 {%0, %1}, %2;" : "=f"(o.x), "=f"(o.y) : "l"(acc[i][0]));
        asm("mov.b64 {%0, %1}, %2;" : "=f"(o.z), "=f"(o.w) : "l"(acc[i][1]));
        *(float4*)&C[(size_t)(r0 + ty * 4 + i) * NC + c0 + tx * 4] = o;
    }
}

// ---------------- src/dst projections: one warp per (head,row) --------------
template<int F, int LAYER>
__global__ void srcdst_kernel(const float* __restrict__ a_src,
                              const float* __restrict__ a_dst) {
    const float* Hm = (LAYER == 1) ? g_h1 : g_h2;
    float* so = (LAYER == 1) ? g_src1 : g_src2;
    float* dso = (LAYER == 1) ? g_dst1 : g_dst2;
    int gw   = (blockIdx.x * blockDim.x + threadIdx.x) >> 5;
    int lane = threadIdx.x & 31;
    int hh = gw / GN, n = gw % GN;
    const float* row = Hm + ((size_t)hh * GN + n) * F;
    float s = 0.f, d = 0.f;
    #pragma unroll
    for (int c = lane; c < F; c += 32) {
        float v = row[c];
        s += v * a_src[hh * F + c];
        d += v * a_dst[hh * F + c];
    }
    #pragma unroll
    for (int o = 16; o; o >>= 1) {
        s += __shfl_xor_sync(0xffffffffu, s, o);
        d += __shfl_xor_sync(0xffffffffu, d, o);
    }
    if (lane == 0) { so[gw] = s; dso[gw] = d; }
}

// ---------------- per-head max over dst (numerical safety) ------------------
template<int LAYER>
__global__ void maxdst_kernel() {
    const float* dv = (LAYER == 1) ? g_dst1 : g_dst2;
    const float* d = dv + (size_t)blockIdx.x * GN;
    __shared__ float red[256];
    float m = -1e30f;
    for (int i = threadIdx.x; i < GN; i += 256) m = fmaxf(m, d[i]);
    red[threadIdx.x] = m;
    __syncthreads();
    for (int s = 128; s > 0; s >>= 1) {
        if (threadIdx.x < s) red[threadIdx.x] = fmaxf(red[threadIdx.x], red[threadIdx.x + s]);
        __syncthreads();
    }
    if (threadIdx.x == 0) g_mdst[((LAYER == 1) ? 0 : NH) + blockIdx.x] = red[0];
}

// ---------------- fused masked-softmax attention + ELU ----------------------
// Block: 32 rows x full F. Loop over 32-wide j tiles.
// phase1: p = adj_bit * exp(lrelu(src_i+dst_j) - m_i) into smem + denom partial
// phase2: acc += p * h_j  via packed fma.rn.f32x2
template<int F, int LAYER>
__global__ __launch_bounds__(256) void attn_kernel(float* __restrict__ dout) {
    constexpr int BM = 32, BN = 32;
    constexpr int CPL = F / 32;      // cols per lane (4 or 2)
    constexpr int NV  = CPL / 2;     // f32x2 accumulators per row (2 or 1)

    const float* Hmat = (LAYER == 1) ? g_h1 : g_h2;
    const float* srcv = (LAYER == 1) ? g_src1 : g_src2;
    const float* dstv = (LAYER == 1) ? g_dst1 : g_dst2;

    const int h  = blockIdx.y;
    const int i0 = blockIdx.x * BM;
    const float* Hh   = Hmat + (size_t)h * GN * F;
    const float* srch = srcv + (size_t)h * GN;
    const float* dsth = dstv + (size_t)h * GN;
    const float  md   = g_mdst[(LAYER == 1) ? h : NH];

    __shared__ float h_s[BN * F];
    __shared__ float p_s[BM][BN + 1];
    __shared__ float red_s[BM][8];
    __shared__ float denom_s[BM];

    const int tid  = threadIdx.x;
    const int lane = tid & 31, w = tid >> 5;
    const int pr = tid >> 3, pjb = tid & 7;    // phase-1 mapping: row, j-group

    const float srcr = srch[i0 + pr];
    float tmp = srcr + md;
    const float mrow = tmp > 0.f ? tmp : ALPHA * tmp;   // >= true row max
    float dpart = 0.f;

    unsigned long long acc[4][NV] = {};
    const unsigned* adjRow = g_adj + (size_t)(i0 + pr) * (GN / 32);

    for (int jt = 0; jt < GN / BN; jt++) {
        const int j0 = jt * BN;
        __syncthreads();                       // prev phase2 done with h_s/p_s
        {   // load h tile (coalesced float4)
            const float4* gp = (const float4*)(Hh + (size_t)j0 * F);
            float4* sp = (float4*)h_s;
            #pragma unroll
            for (int i = tid; i < BN * F / 4; i += 256) sp[i] = gp[i];
        }
        {   // phase 1: 4 p-entries per thread
            unsigned aw = __ldg(&adjRow[jt]);
            #pragma unroll
            for (int k = 0; k < 4; k++) {
                int j = pjb + 8 * k;
                float e = srcr + __ldg(&dsth[j0 + j]);
                e = e > 0.f ? e : ALPHA * e;
                float p = ((aw >> j) & 1u) ? __expf(e - mrow) : 0.f;
                p_s[pr][j] = p;
                dpart += p;
            }
        }
        __syncthreads();
        {   // phase 2: rank-BN update, warp w owns rows w*4..w*4+3
            const int r0 = w * 4;
            #pragma unroll 8
            for (int jl = 0; jl < BN; jl++) {
                unsigned long long hv[NV];
                if (NV == 2) {
                    ulonglong2 t = *(const ulonglong2*)&h_s[jl * F + lane * 4];
                    hv[0] = t.x; hv[1] = t.y;
                } else {
                    hv[0] = *(const unsigned long long*)&h_s[jl * F + lane * 2];
                }
                #pragma unroll
                for (int r = 0; r < 4; r++) {
                    float p = p_s[r0 + r][jl];
                    unsigned long long pp;
                    asm("mov.b64 %0, {%1, %1};" : "=l"(pp) : "f"(p));
                    #pragma unroll
                    for (int v = 0; v < NV; v++)
                        asm("fma.rn.f32x2 %0, %1, %2, %0;"
                            : "+l"(acc[r][v]) : "l"(pp), "l"(hv[v]));
                }
            }
        }
    }

    // denominators
    red_s[pr][pjb] = dpart;
    __syncthreads();
    if (tid < BM) {
        float s = 0.f;
        #pragma unroll
        for (int k = 0; k < 8; k++) s += red_s[tid][k];
        denom_s[tid] = 1.f / s;
    }
    __syncthreads();

    // epilogue: normalize, ELU, store
    {
        const int r0 = w * 4;
        #pragma unroll
        for (int r = 0; r < 4; r++) {
            int row = i0 + r0 + r;
            float inv = denom_s[r0 + r];
            float o[CPL];
            #pragma unroll
            for (int v = 0; v < NV; v++)
                asm("mov.b64 {%0, %1}, %2;" : "=f"(o[2 * v]), "=f"(o[2 * v + 1]) : "l"(acc[r][v]));
            #pragma unroll
            for (int c = 0; c < CPL; c++) {
                float val = o[c] * inv;
                o[c] = val > 0.f ? val : expm1f(val);
            }
            if constexpr (LAYER == 1) {
                float* op = g_x2 + (size_t)row * (NH * FH) + h * FH + lane * CPL;
                *(float4*)op = make_float4(o[0], o[1], o[2], o[3]);
            } else {
                float* op = dout + (size_t)row * F + lane * CPL;
                *(float2*)op = make_float2(o[0], o[1]);
            }
        }
    }
}

// ---------------- final log_softmax over 64 cols, one warp per row ----------
__global__ void logsoftmax_kernel(float* __restrict__ out) {
    int gw   = (blockIdx.x * blockDim.x + threadIdx.x) >> 5;
    int lane = threadIdx.x & 31;
    if (gw >= GN) return;
    float* row = out + (size_t)gw * FOUT;
    float v0 = row[lane], v1 = row[lane + 32];
    float m = fmaxf(v0, v1);
    #pragma unroll
    for (int o = 16; o; o >>= 1) m = fmaxf(m, __shfl_xor_sync(0xffffffffu, m, o));
    float s = __expf(v0 - m) + __expf(v1 - m);
    #pragma unroll
    for (int o = 16; o; o >>= 1) s += __shfl_xor_sync(0xffffffffu, s, o);
    float lse = m + logf(s);
    row[lane] = v0 - lse;
    row[lane + 32] = v1 - lse;
}

// ---------------- launch ----------------------------------------------------
extern "C" void kernel_launch(void* const* d_in, const int* in_sizes, int n_in,
                              void* d_out, int out_size) {
    const float* features = (const float*)d_in[0];
    const int*   adj      = (const int*)d_in[1];
    const float* W1  = (const float*)d_in[2];
    const float* a1s = (const float*)d_in[3];
    const float* a1d = (const float*)d_in[4];
    const float* W2  = (const float*)d_in[5];
    const float* a2s = (const float*)d_in[6];
    const float* a2d = (const float*)d_in[7];
    float* out = (float*)d_out;

    pack_adj_kernel<<<(GN * GN) / 256, 256>>>(adj);

    // layer 1
    gemm_kernel<FIN, FH, 1><<<dim3(GN / 64, FH / 64, NH), 256>>>(features, W1);
    srcdst_kernel<FH, 1><<<(NH * GN) / 8, 256>>>(a1s, a1d);
    maxdst_kernel<1><<<NH, 256>>>();
    attn_kernel<FH, 1><<<dim3(GN / 32, NH), 256>>>(nullptr);

    // layer 2
    gemm_kernel<NH * FH, FOUT, 2><<<dim3(GN / 64, 1, 1), 256>>>(nullptr, W2);
    srcdst_kernel<FOUT, 2><<<GN / 8, 256>>>(a2s, a2d);
    maxdst_kernel<2><<<1, 256>>>();
    attn_kernel<FOUT, 2><<<dim3(GN / 32, 1), 256>>>(out);

    logsoftmax_kernel<<<GN / 8, 256>>>(out);
}

// round 4
// speedup vs baseline: 1.8528x; 1.8528x over previous
#include <cuda_runtime.h>
#include <cuda_fp16.h>
#include <cstdint>
#include <math.h>

#define GN   4096
#define FIN  512
#define FH   128
#define NH   4
#define FOUT 64
#define ALPHA 0.2f

// ---------------- scratch (device globals; no allocations allowed) ----------
__device__ float  g_h1[NH * GN * FH];       // [h][n][f] fp32, 8 MB
__device__ __half g_h1h[NH * GN * FH];      // [h][n][f] fp16, 4 MB
__device__ float  g_h2[GN * FOUT];          // 1 MB
__device__ __half g_h2h[GN * FOUT];         // 0.5 MB
__device__ float  g_src1[NH * GN];
__device__ float  g_dst1[NH * GN];
__device__ float  g_src2[GN];
__device__ float  g_dst2[GN];
__device__ float  g_mdst[NH + 1];
__device__ unsigned g_adj[GN * GN / 32];    // bit mask, 2 MB (L2 resident)
__device__ float  g_x2[GN * (NH * FH)];     // layer-1 output, 8 MB

// ---------------- PTX helpers (sm_80-era, safe for sm_100 target) -----------
__device__ __forceinline__ unsigned s2u(const void* p) {
    unsigned a;
    asm("{ .reg .u64 t; cvta.to.shared.u64 t, %1; cvt.u32.u64 %0, t; }"
        : "=r"(a) : "l"(p));
    return a;
}

__device__ __forceinline__ void ldsm4(unsigned* d, unsigned addr) {
    asm volatile("ldmatrix.sync.aligned.m8n8.x4.shared.b16 {%0,%1,%2,%3}, [%4];"
                 : "=r"(d[0]), "=r"(d[1]), "=r"(d[2]), "=r"(d[3]) : "r"(addr));
}

__device__ __forceinline__ void ldsm4t(unsigned* d, unsigned addr) {
    asm volatile("ldmatrix.sync.aligned.m8n8.x4.trans.shared.b16 {%0,%1,%2,%3}, [%4];"
                 : "=r"(d[0]), "=r"(d[1]), "=r"(d[2]), "=r"(d[3]) : "r"(addr));
}

__device__ __forceinline__ void mma16816(float* c, const unsigned* a,
                                         unsigned b0, unsigned b1) {
    asm volatile(
        "mma.sync.aligned.m16n8k16.row.col.f32.f16.f16.f32 "
        "{%0,%1,%2,%3}, {%4,%5,%6,%7}, {%8,%9}, {%0,%1,%2,%3};"
        : "+f"(c[0]), "+f"(c[1]), "+f"(c[2]), "+f"(c[3])
        : "r"(a[0]), "r"(a[1]), "r"(a[2]), "r"(a[3]), "r"(b0), "r"(b1));
}

// ---------------- adjacency pack: int32 -> bit mask -------------------------
__global__ void pack_adj_kernel(const int* __restrict__ adj) {
    int i = blockIdx.x * blockDim.x + threadIdx.x;
    unsigned bal = __ballot_sync(0xffffffffu, adj[i] > 0);
    if ((threadIdx.x & 31) == 0) g_adj[i >> 5] = bal;
}

// ---------------- GEMM: C[M,NC] = A[M,K] @ B[K,NC] (per-head via blockIdx.z)
// Writes fp32 C and an fp16 copy (for the MMA attention B operand).
template<int K, int NC, int LAYER>
__global__ __launch_bounds__(256) void gemm_kernel(const float* __restrict__ Aarg,
                                                   const float* __restrict__ Wall) {
    constexpr int BM = 64, BK = 16;
    const float* A = (LAYER == 1) ? Aarg : g_x2;
    const float* B = Wall + (size_t)blockIdx.z * K * NC;
    float*  C  = (LAYER == 1) ? (g_h1  + (size_t)blockIdx.z * GN * NC) : g_h2;
    __half* Ch = (LAYER == 1) ? (g_h1h + (size_t)blockIdx.z * GN * NC) : g_h2h;
    const int r0 = blockIdx.x * BM;
    const int c0 = blockIdx.y * 64;

    __shared__ float a_s[BK][BM + 1];
    __shared__ float b_s[BK][64];

    const int tid = threadIdx.x;
    const int tx = tid & 15, ty = tid >> 4;

    unsigned long long acc[4][2] = {};

    for (int k0 = 0; k0 < K; k0 += BK) {
        __syncthreads();
        {
            int ar = tid >> 2;
            int ak = (tid & 3) * 4;
            float4 v = *(const float4*)&A[(size_t)(r0 + ar) * K + k0 + ak];
            a_s[ak + 0][ar] = v.x; a_s[ak + 1][ar] = v.y;
            a_s[ak + 2][ar] = v.z; a_s[ak + 3][ar] = v.w;
        }
        {
            int bk = tid >> 4;
            int bc = (tid & 15) * 4;
            *(float4*)&b_s[bk][bc] = *(const float4*)&B[(size_t)(k0 + bk) * NC + c0 + bc];
        }
        __syncthreads();
        #pragma unroll
        for (int kk = 0; kk < BK; kk++) {
            ulonglong2 bv = *(const ulonglong2*)&b_s[kk][tx * 4];
            #pragma unroll
            for (int i = 0; i < 4; i++) {
                float av = a_s[kk][ty * 4 + i];
                unsigned long long ap;
                asm("mov.b64 %0, {%1, %1};" : "=l"(ap) : "f"(av));
                asm("fma.rn.f32x2 %0, %1, %2, %0;" : "+l"(acc[i][0]) : "l"(ap), "l"(bv.x));
                asm("fma.rn.f32x2 %0, %1, %2, %0;" : "+l"(acc[i][1]) : "l"(ap), "l"(bv.y));
            }
        }
    }
    #pragma unroll
    for (int i = 0; i < 4; i++) {
        float4 o;
        asm("mov.b64 {%0, %1}, %2;" : "=f"(o.x), "=f"(o.y) : "l"(acc[i][0]));
        asm("mov.b64 {%0, %1}, %2;" : "=f"(o.z), "=f"(o.w) : "l"(acc[i][1]));
        size_t idx = (size_t)(r0 + ty * 4 + i) * NC + c0 + tx * 4;
        *(float4*)&C[idx] = o;
        __half2 h01 = __floats2half2_rn(o.x, o.y);
        __half2 h23 = __floats2half2_rn(o.z, o.w);
        *(__half2*)&Ch[idx]     = h01;
        *(__half2*)&Ch[idx + 2] = h23;
    }
}

// ---------------- src/dst projections: one warp per (head,row) --------------
template<int F, int LAYER>
__global__ void srcdst_kernel(const float* __restrict__ a_src,
                              const float* __restrict__ a_dst) {
    const float* Hm = (LAYER == 1) ? g_h1 : g_h2;
    float* so  = (LAYER == 1) ? g_src1 : g_src2;
    float* dso = (LAYER == 1) ? g_dst1 : g_dst2;
    int gw   = (blockIdx.x * blockDim.x + threadIdx.x) >> 5;
    int lane = threadIdx.x & 31;
    int hh = gw / GN, n = gw % GN;
    const float* row = Hm + ((size_t)hh * GN + n) * F;
    float s = 0.f, d = 0.f;
    for (int c = lane; c < F; c += 32) {
        float v = row[c];
        s += v * a_src[hh * F + c];
        d += v * a_dst[hh * F + c];
    }
    for (int o = 16; o; o >>= 1) {
        s += __shfl_xor_sync(0xffffffffu, s, o);
        d += __shfl_xor_sync(0xffffffffu, d, o);
    }
    if (lane == 0) { so[gw] = s; dso[gw] = d; }
}

// ---------------- per-head max over dst (numerical safety) ------------------
template<int LAYER>
__global__ void maxdst_kernel() {
    const float* dv = (LAYER == 1) ? g_dst1 : g_dst2;
    const float* d = dv + (size_t)blockIdx.x * GN;
    __shared__ float red[256];
    float m = -1e30f;
    for (int i = threadIdx.x; i < GN; i += 256) m = fmaxf(m, d[i]);
    red[threadIdx.x] = m;
    __syncthreads();
    for (int s = 128; s > 0; s >>= 1) {
        if (threadIdx.x < s) red[threadIdx.x] = fmaxf(red[threadIdx.x], red[threadIdx.x + s]);
        __syncthreads();
    }
    if (threadIdx.x == 0) g_mdst[((LAYER == 1) ? 0 : NH) + blockIdx.x] = red[0];
}

// ---------------- fused masked-softmax attention via mma.sync (HMMA) --------
// Block: BM query rows, K-tiles of 128 neighbors. Phase 1 generates the fp16
// P tile in smem (+ fp32 denom partials); phase 2 stages fp16 H and runs
// m16n8k16 f16->f32 MMAs, accumulating in registers across all 32 K-tiles.
// Epilogue normalizes by exact fp32 denominators, applies ELU, stores fp32.
template<int BM, int NB, int LAYER>
__global__ __launch_bounds__(256) void attn_mma_kernel(float* __restrict__ dout) {
    constexpr int KT  = 128;
    constexpr int TPR = 256 / BM;          // threads per row (P-gen)
    constexpr int JPT = KT / TPR;          // j entries per thread per tile
    constexpr int WPT = JPT / 32;          // adjacency words per thread per tile
    constexpr int WM  = BM / 4;            // warp M tile (32 or 16)
    constexpr int WN  = NB / 2;            // warp N tile (64 or 32)
    constexpr int MI  = WM / 16;           // m16 blocks per warp (2 or 1)
    constexpr int N16 = WN / 16;           // n16 blocks per warp (4 or 2)
    constexpr int PSTR = KT + 8;           // P smem stride (halfs) = 136
    constexpr int HSTR = NB + 8;           // H smem stride (halfs)

    extern __shared__ __align__(16) char smem_c[];
    float* dpart_s = (float*)smem_c;                    // [256]
    float* inv_s   = (float*)(smem_c + 1024);           // [BM]
    char*  p_s     = smem_c + 2048;                     // BM x PSTR halfs
    char*  h_s     = p_s + BM * PSTR * 2;               // KT x HSTR halfs

    const unsigned sbase = s2u(smem_c);
    const unsigned pb32  = sbase + 2048;
    const unsigned hb32  = pb32 + BM * PSTR * 2;

    const int tid = threadIdx.x;
    const int h   = blockIdx.y;
    const int i0  = blockIdx.x * BM;

    const float* srcv = (LAYER == 1) ? (g_src1 + (size_t)h * GN) : g_src2;
    const float* dstv = (LAYER == 1) ? (g_dst1 + (size_t)h * GN) : g_dst2;
    const __half* Hh  = (LAYER == 1) ? (g_h1h + (size_t)h * GN * FH) : g_h2h;
    const float md = g_mdst[(LAYER == 1) ? h : NH];

    // P-gen mapping
    const int r   = tid / TPR;
    const int sub = tid % TPR;
    const float srcr = srcv[i0 + r];
    float t0 = srcr + md;
    const float mrow = (t0 > 0.f) ? t0 : (ALPHA * t0);   // >= true row max
    const unsigned* adjR = g_adj + (size_t)(i0 + r) * (GN / 32);
    float dpart = 0.f;

    // MMA mapping
    const int w = tid >> 5, lane = tid & 31;
    const int wm = (w & 3) * WM;
    const int wn = (w >> 2) * WN;
    float acc[MI][2 * N16][4];
    #pragma unroll
    for (int a = 0; a < MI; a++)
        #pragma unroll
        for (int b = 0; b < 2 * N16; b++)
            #pragma unroll
            for (int c = 0; c < 4; c++) acc[a][b][c] = 0.f;

    for (int jt = 0; jt < GN / KT; jt++) {
        const int j0 = jt * KT;
        __syncthreads();        // prior MMA phase done with smem
        {   // phase 1: P tile
            unsigned aw[WPT];
            #pragma unroll
            for (int q = 0; q < WPT; q++)
                aw[q] = __ldg(adjR + jt * (KT / 32) + sub * WPT + q);
            const float* dstp = dstv + j0 + sub * JPT;
            char* prow = p_s + r * (PSTR * 2) + sub * JPT * 2;
            #pragma unroll 4
            for (int kk = 0; kk < JPT / 2; kk++) {
                float2 dv = *(const float2*)(dstp + 2 * kk);
                float e0 = srcr + dv.x; e0 = (e0 > 0.f) ? e0 : (ALPHA * e0);
                float e1 = srcr + dv.y; e1 = (e1 > 0.f) ? e1 : (ALPHA * e1);
                unsigned wsel = aw[kk >> 4];
                int sh = (2 * kk) & 31;
                float p0 = ((wsel >> sh) & 1u)       ? __expf(e0 - mrow) : 0.f;
                float p1 = ((wsel >> (sh + 1)) & 1u) ? __expf(e1 - mrow) : 0.f;
                dpart += p0 + p1;
                *(__half2*)(prow + 4 * kk) = __floats2half2_rn(p0, p1);
            }
        }
        {   // phase 1b: H tile (KT rows x NB halfs), 16B chunks
            for (int c = tid; c < KT * NB / 8; c += 256) {
                int row = c / (NB / 8), ch = c % (NB / 8);
                uint4 v = *(const uint4*)(Hh + (size_t)(j0 + row) * NB + ch * 8);
                *(uint4*)(h_s + row * (HSTR * 2) + ch * 16) = v;
            }
        }
        __syncthreads();
        {   // phase 2: MMAs over this K tile
            #pragma unroll
            for (int k16 = 0; k16 < KT / 16; k16++) {
                unsigned afr[MI][4];
                #pragma unroll
                for (int mi = 0; mi < MI; mi++)
                    ldsm4(afr[mi], pb32 +
                          ((wm + mi * 16 + (lane & 15)) * PSTR +
                           k16 * 16 + (lane >> 4) * 8) * 2);
                #pragma unroll
                for (int nj = 0; nj < N16; nj++) {
                    unsigned bfr[4];
                    ldsm4t(bfr, hb32 +
                           ((k16 * 16 + (lane & 15)) * HSTR +
                            wn + nj * 16 + (lane >> 4) * 8) * 2);
                    #pragma unroll
                    for (int mi = 0; mi < MI; mi++) {
                        mma16816(acc[mi][2 * nj],     afr[mi], bfr[0], bfr[1]);
                        mma16816(acc[mi][2 * nj + 1], afr[mi], bfr[2], bfr[3]);
                    }
                }
            }
        }
    }

    // denominators (exact fp32)
    dpart_s[tid] = dpart;
    __syncthreads();
    if (tid < BM) {
        float s = 0.f;
        #pragma unroll
        for (int q = 0; q < TPR; q++) s += dpart_s[tid * TPR + q];
        inv_s[tid] = 1.f / s;
    }
    __syncthreads();

    // epilogue: normalize + ELU + store fp32
    const int g = lane >> 2, tig = lane & 3;
    #pragma unroll
    for (int mi = 0; mi < MI; mi++) {
        int rr0 = wm + mi * 16 + g;
        float inv0 = inv_s[rr0], inv1 = inv_s[rr0 + 8];
        #pragma unroll
        for (int f = 0; f < 2 * N16; f++) {
            int col = wn + f * 8 + tig * 2;
            float v0 = acc[mi][f][0] * inv0;
            float v1 = acc[mi][f][1] * inv0;
            float v2 = acc[mi][f][2] * inv1;
            float v3 = acc[mi][f][3] * inv1;
            v0 = (v0 > 0.f) ? v0 : expm1f(v0);
            v1 = (v1 > 0.f) ? v1 : expm1f(v1);
            v2 = (v2 > 0.f) ? v2 : expm1f(v2);
            v3 = (v3 > 0.f) ? v3 : expm1f(v3);
            if (LAYER == 1) {
                float* o0 = g_x2 + (size_t)(i0 + rr0) * (NH * FH) + h * FH + col;
                float* o1 = g_x2 + (size_t)(i0 + rr0 + 8) * (NH * FH) + h * FH + col;
                *(float2*)o0 = make_float2(v0, v1);
                *(float2*)o1 = make_float2(v2, v3);
            } else {
                float* o0 = dout + (size_t)(i0 + rr0) * FOUT + col;
                float* o1 = dout + (size_t)(i0 + rr0 + 8) * FOUT + col;
                *(float2*)o0 = make_float2(v0, v1);
                *(float2*)o1 = make_float2(v2, v3);
            }
        }
    }
}

// ---------------- final log_softmax over 64 cols, one warp per row ----------
__global__ void logsoftmax_kernel(float* __restrict__ out) {
    int gw   = (blockIdx.x * blockDim.x + threadIdx.x) >> 5;
    int lane = threadIdx.x & 31;
    if (gw >= GN) return;
    float* row = out + (size_t)gw * FOUT;
    float v0 = row[lane], v1 = row[lane + 32];
    float m = fmaxf(v0, v1);
    for (int o = 16; o; o >>= 1) m = fmaxf(m, __shfl_xor_sync(0xffffffffu, m, o));
    float s = __expf(v0 - m) + __expf(v1 - m);
    for (int o = 16; o; o >>= 1) s += __shfl_xor_sync(0xffffffffu, s, o);
    float lse = m + logf(s);
    row[lane] = v0 - lse;
    row[lane + 32] = v1 - lse;
}

// ---------------- launch ----------------------------------------------------
extern "C" void kernel_launch(void* const* d_in, const int* in_sizes, int n_in,
                              void* d_out, int out_size) {
    const float* features = (const float*)d_in[0];
    const int*   adj      = (const int*)d_in[1];
    const float* W1  = (const float*)d_in[2];
    const float* a1s = (const float*)d_in[3];
    const float* a1d = (const float*)d_in[4];
    const float* W2  = (const float*)d_in[5];
    const float* a2s = (const float*)d_in[6];
    const float* a2d = (const float*)d_in[7];
    float* out = (float*)d_out;

    const int SMEM1 = 2048 + 128 * 136 * 2 + 128 * 136 * 2;  // 71680
    const int SMEM2 = 2048 + 64 * 136 * 2 + 128 * 72 * 2;    // 37888
    cudaFuncSetAttribute(attn_mma_kernel<128, FH, 1>,
                         cudaFuncAttributeMaxDynamicSharedMemorySize, SMEM1);
    cudaFuncSetAttribute(attn_mma_kernel<64, FOUT, 2>,
                         cudaFuncAttributeMaxDynamicSharedMemorySize, SMEM2);

    pack_adj_kernel<<<(GN * GN) / 256, 256>>>(adj);

    // layer 1
    gemm_kernel<FIN, FH, 1><<<dim3(GN / 64, FH / 64, NH), 256>>>(features, W1);
    srcdst_kernel<FH, 1><<<(NH * GN) / 8, 256>>>(a1s, a1d);
    maxdst_kernel<1><<<NH, 256>>>();
    attn_mma_kernel<128, FH, 1><<<dim3(GN / 128, NH), 256, SMEM1>>>(nullptr);

    // layer 2
    gemm_kernel<NH * FH, FOUT, 2><<<dim3(GN / 64, 1, 1), 256>>>(nullptr, W2);
    srcdst_kernel<FOUT, 2><<<GN / 8, 256>>>(a2s, a2d);
    maxdst_kernel<2><<<1, 256>>>();
    attn_mma_kernel<64, FOUT, 2><<<dim3(GN / 64, 1), 256, SMEM2>>>(out);

    logsoftmax_kernel<<<GN / 8, 256>>>(out);
}

// round 10
// speedup vs baseline: 1.8541x; 1.0007x over previous
#include <cuda_runtime.h>
#include <cuda_fp16.h>
#include <cstdint>
#include <math.h>

#define GN   4096
#define FIN  512
#define FH   128
#define NH   4
#define FOUT 64
#define ALPHA 0.2f

// ---------------- scratch (device globals; no allocations allowed) ----------
__device__ float  g_h1[NH * GN * FH];       // [h][n][f] fp32, 8 MB
__device__ __half g_h1h[NH * GN * FH];      // [h][n][f] fp16, 4 MB
__device__ float  g_h2[GN * FOUT];          // 1 MB
__device__ __half g_h2h[GN * FOUT];         // 0.5 MB
__device__ float  g_src1[NH * GN];
__device__ float  g_dst1[NH * GN];
__device__ float  g_src2[GN];
__device__ float  g_dst2[GN];
__device__ float  g_mdst[NH + 1];
__device__ unsigned g_adj[GN * GN / 32];    // bit mask, 2 MB (L2 resident)
__device__ float  g_x2[GN * (NH * FH)];     // layer-1 output, 8 MB

// ---------------- PTX helpers (sm_80-era, safe for sm_100 target) -----------
__device__ __forceinline__ unsigned s2u(const void* p) {
    unsigned a;
    asm("{ .reg .u64 t; cvta.to.shared.u64 t, %1; cvt.u32.u64 %0, t; }"
        : "=r"(a) : "l"(p));
    return a;
}

__device__ __forceinline__ void ldsm4(unsigned* d, unsigned addr) {
    asm volatile("ldmatrix.sync.aligned.m8n8.x4.shared.b16 {%0,%1,%2,%3}, [%4];"
                 : "=r"(d[0]), "=r"(d[1]), "=r"(d[2]), "=r"(d[3]) : "r"(addr));
}

__device__ __forceinline__ void ldsm4t(unsigned* d, unsigned addr) {
    asm volatile("ldmatrix.sync.aligned.m8n8.x4.trans.shared.b16 {%0,%1,%2,%3}, [%4];"
                 : "=r"(d[0]), "=r"(d[1]), "=r"(d[2]), "=r"(d[3]) : "r"(addr));
}

__device__ __forceinline__ void mma16816(float* c, const unsigned* a,
                                         unsigned b0, unsigned b1) {
    asm volatile(
        "mma.sync.aligned.m16n8k16.row.col.f32.f16.f16.f32 "
        "{%0,%1,%2,%3}, {%4,%5,%6,%7}, {%8,%9}, {%0,%1,%2,%3};"
        : "+f"(c[0]), "+f"(c[1]), "+f"(c[2]), "+f"(c[3])
        : "r"(a[0]), "r"(a[1]), "r"(a[2]), "r"(a[3]), "r"(b0), "r"(b1));
}

// ---------------- adjacency pack: int32 -> bit mask -------------------------
__global__ void pack_adj_kernel(const int* __restrict__ adj) {
    int i = blockIdx.x * blockDim.x + threadIdx.x;
    unsigned bal = __ballot_sync(0xffffffffu, adj[i] > 0);
    if ((threadIdx.x & 31) == 0) g_adj[i >> 5] = bal;
}

// ---------------- GEMM: C[M,NC] = A[M,K] @ B[K,NC] (per-head via blockIdx.z)
// Writes fp32 C and an fp16 copy (for the MMA attention B operand).
template<int K, int NC, int LAYER>
__global__ __launch_bounds__(256) void gemm_kernel(const float* __restrict__ Aarg,
                                                   const float* __restrict__ Wall) {
    constexpr int BM = 64, BK = 16;
    const float* A = (LAYER == 1) ? Aarg : g_x2;
    const float* B = Wall + (size_t)blockIdx.z * K * NC;
    float*  C  = (LAYER == 1) ? (g_h1  + (size_t)blockIdx.z * GN * NC) : g_h2;
    __half* Ch = (LAYER == 1) ? (g_h1h + (size_t)blockIdx.z * GN * NC) : g_h2h;
    const int r0 = blockIdx.x * BM;
    const int c0 = blockIdx.y * 64;

    __shared__ float a_s[BK][BM + 1];
    __shared__ float b_s[BK][64];

    const int tid = threadIdx.x;
    const int tx = tid & 15, ty = tid >> 4;

    unsigned long long acc[4][2] = {};

    for (int k0 = 0; k0 < K; k0 += BK) {
        __syncthreads();
        {
            int ar = tid >> 2;
            int ak = (tid & 3) * 4;
            float4 v = *(const float4*)&A[(size_t)(r0 + ar) * K + k0 + ak];
            a_s[ak + 0][ar] = v.x; a_s[ak + 1][ar] = v.y;
            a_s[ak + 2][ar] = v.z; a_s[ak + 3][ar] = v.w;
        }
        {
            int bk = tid >> 4;
            int bc = (tid & 15) * 4;
            *(float4*)&b_s[bk][bc] = *(const float4*)&B[(size_t)(k0 + bk) * NC + c0 + bc];
        }
        __syncthreads();
        #pragma unroll
        for (int kk = 0; kk < BK; kk++) {
            ulonglong2 bv = *(const ulonglong2*)&b_s[kk][tx * 4];
            #pragma unroll
            for (int i = 0; i < 4; i++) {
                float av = a_s[kk][ty * 4 + i];
                unsigned long long ap;
                asm("mov.b64 %0, {%1, %1};" : "=l"(ap) : "f"(av));
                asm("fma.rn.f32x2 %0, %1, %2, %0;" : "+l"(acc[i][0]) : "l"(ap), "l"(bv.x));
                asm("fma.rn.f32x2 %0, %1, %2, %0;" : "+l"(acc[i][1]) : "l"(ap), "l"(bv.y));
            }
        }
    }
    #pragma unroll
    for (int i = 0; i < 4; i++) {
        float4 o;
        asm("mov.b64 {%0, %1}, %2;" : "=f"(o.x), "=f"(o.y) : "l"(acc[i][0]));
        asm("mov.b64 {%0, %1}, %2;" : "=f"(o.z), "=f"(o.w) : "l"(acc[i][1]));
        size_t idx = (size_t)(r0 + ty * 4 + i) * NC + c0 + tx * 4;
        *(float4*)&C[idx] = o;
        __half2 h01 = __floats2half2_rn(o.x, o.y);
        __half2 h23 = __floats2half2_rn(o.z, o.w);
        *(__half2*)&Ch[idx]     = h01;
        *(__half2*)&Ch[idx + 2] = h23;
    }
}

// ---------------- src/dst projections: one warp per (head,row) --------------
template<int F, int LAYER>
__global__ void srcdst_kernel(const float* __restrict__ a_src,
                              const float* __restrict__ a_dst) {
    const float* Hm = (LAYER == 1) ? g_h1 : g_h2;
    float* so  = (LAYER == 1) ? g_src1 : g_src2;
    float* dso = (LAYER == 1) ? g_dst1 : g_dst2;
    int gw   = (blockIdx.x * blockDim.x + threadIdx.x) >> 5;
    int lane = threadIdx.x & 31;
    int hh = gw / GN, n = gw % GN;
    const float* row = Hm + ((size_t)hh * GN + n) * F;
    float s = 0.f, d = 0.f;
    for (int c = lane; c < F; c += 32) {
        float v = row[c];
        s += v * a_src[hh * F + c];
        d += v * a_dst[hh * F + c];
    }
    for (int o = 16; o; o >>= 1) {
        s += __shfl_xor_sync(0xffffffffu, s, o);
        d += __shfl_xor_sync(0xffffffffu, d, o);
    }
    if (lane == 0) { so[gw] = s; dso[gw] = d; }
}

// ---------------- per-head max over dst (numerical safety) ------------------
template<int LAYER>
__global__ void maxdst_kernel() {
    const float* dv = (LAYER == 1) ? g_dst1 : g_dst2;
    const float* d = dv + (size_t)blockIdx.x * GN;
    __shared__ float red[256];
    float m = -1e30f;
    for (int i = threadIdx.x; i < GN; i += 256) m = fmaxf(m, d[i]);
    red[threadIdx.x] = m;
    __syncthreads();
    for (int s = 128; s > 0; s >>= 1) {
        if (threadIdx.x < s) red[threadIdx.x] = fmaxf(red[threadIdx.x], red[threadIdx.x + s]);
        __syncthreads();
    }
    if (threadIdx.x == 0) g_mdst[((LAYER == 1) ? 0 : NH) + blockIdx.x] = red[0];
}

// ---------------- fused masked-softmax attention via mma.sync (HMMA) --------
// Block: BM query rows, K-tiles of 128 neighbors. Phase 1 generates the fp16
// P tile in smem (+ fp32 denom partials); phase 2 stages fp16 H and runs
// m16n8k16 f16->f32 MMAs, accumulating in registers across all 32 K-tiles.
// Epilogue normalizes by exact fp32 denominators, applies ELU, stores fp32.
template<int BM, int NB, int LAYER>
__global__ __launch_bounds__(256) void attn_mma_kernel(float* __restrict__ dout) {
    constexpr int KT  = 128;
    constexpr int TPR = 256 / BM;          // threads per row (P-gen)
    constexpr int JPT = KT / TPR;          // j entries per thread per tile
    constexpr int WPT = JPT / 32;          // adjacency words per thread per tile
    constexpr int WM  = BM / 4;            // warp M tile (32 or 16)
    constexpr int WN  = NB / 2;            // warp N tile (64 or 32)
    constexpr int MI  = WM / 16;           // m16 blocks per warp (2 or 1)
    constexpr int N16 = WN / 16;           // n16 blocks per warp (4 or 2)
    constexpr int PSTR = KT + 8;           // P smem stride (halfs) = 136
    constexpr int HSTR = NB + 8;           // H smem stride (halfs)

    extern __shared__ __align__(16) char smem_c[];
    float* dpart_s = (float*)smem_c;                    // [256]
    float* inv_s   = (float*)(smem_c + 1024);           // [BM]
    char*  p_s     = smem_c + 2048;                     // BM x PSTR halfs
    char*  h_s     = p_s + BM * PSTR * 2;               // KT x HSTR halfs

    const unsigned sbase = s2u(smem_c);
    const unsigned pb32  = sbase + 2048;
    const unsigned hb32  = pb32 + BM * PSTR * 2;

    const int tid = threadIdx.x;
    const int h   = blockIdx.y;
    const int i0  = blockIdx.x * BM;

    const float* srcv = (LAYER == 1) ? (g_src1 + (size_t)h * GN) : g_src2;
    const float* dstv = (LAYER == 1) ? (g_dst1 + (size_t)h * GN) : g_dst2;
    const __half* Hh  = (LAYER == 1) ? (g_h1h + (size_t)h * GN * FH) : g_h2h;
    const float md = g_mdst[(LAYER == 1) ? h : NH];

    // P-gen mapping
    const int r   = tid / TPR;
    const int sub = tid % TPR;
    const float srcr = srcv[i0 + r];
    float t0 = srcr + md;
    const float mrow = (t0 > 0.f) ? t0 : (ALPHA * t0);   // >= true row max
    const unsigned* adjR = g_adj + (size_t)(i0 + r) * (GN / 32);
    float dpart = 0.f;

    // MMA mapping
    const int w = tid >> 5, lane = tid & 31;
    const int wm = (w & 3) * WM;
    const int wn = (w >> 2) * WN;
    float acc[MI][2 * N16][4];
    #pragma unroll
    for (int a = 0; a < MI; a++)
        #pragma unroll
        for (int b = 0; b < 2 * N16; b++)
            #pragma unroll
            for (int c = 0; c < 4; c++) acc[a][b][c] = 0.f;

    for (int jt = 0; jt < GN / KT; jt++) {
        const int j0 = jt * KT;
        __syncthreads();        // prior MMA phase done with smem
        {   // phase 1: P tile
            unsigned aw[WPT];
            #pragma unroll
            for (int q = 0; q < WPT; q++)
                aw[q] = __ldg(adjR + jt * (KT / 32) + sub * WPT + q);
            const float* dstp = dstv + j0 + sub * JPT;
            char* prow = p_s + r * (PSTR * 2) + sub * JPT * 2;
            #pragma unroll 4
            for (int kk = 0; kk < JPT / 2; kk++) {
                float2 dv = *(const float2*)(dstp + 2 * kk);
                float e0 = srcr + dv.x; e0 = (e0 > 0.f) ? e0 : (ALPHA * e0);
                float e1 = srcr + dv.y; e1 = (e1 > 0.f) ? e1 : (ALPHA * e1);
                unsigned wsel = aw[kk >> 4];
                int sh = (2 * kk) & 31;
                float p0 = ((wsel >> sh) & 1u)       ? __expf(e0 - mrow) : 0.f;
                float p1 = ((wsel >> (sh + 1)) & 1u) ? __expf(e1 - mrow) : 0.f;
                dpart += p0 + p1;
                *(__half2*)(prow + 4 * kk) = __floats2half2_rn(p0, p1);
            }
        }
        {   // phase 1b: H tile (KT rows x NB halfs), 16B chunks
            for (int c = tid; c < KT * NB / 8; c += 256) {
                int row = c / (NB / 8), ch = c % (NB / 8);
                uint4 v = *(const uint4*)(Hh + (size_t)(j0 + row) * NB + ch * 8);
                *(uint4*)(h_s + row * (HSTR * 2) + ch * 16) = v;
            }
        }
        __syncthreads();
        {   // phase 2: MMAs over this K tile
            #pragma unroll
            for (int k16 = 0; k16 < KT / 16; k16++) {
                unsigned afr[MI][4];
                #pragma unroll
                for (int mi = 0; mi < MI; mi++)
                    ldsm4(afr[mi], pb32 +
                          ((wm + mi * 16 + (lane & 15)) * PSTR +
                           k16 * 16 + (lane >> 4) * 8) * 2);
                #pragma unroll
                for (int nj = 0; nj < N16; nj++) {
                    unsigned bfr[4];
                    ldsm4t(bfr, hb32 +
                           ((k16 * 16 + (lane & 15)) * HSTR +
                            wn + nj * 16 + (lane >> 4) * 8) * 2);
                    #pragma unroll
                    for (int mi = 0; mi < MI; mi++) {
                        mma16816(acc[mi][2 * nj],     afr[mi], bfr[0], bfr[1]);
                        mma16816(acc[mi][2 * nj + 1], afr[mi], bfr[2], bfr[3]);
                    }
                }
            }
        }
    }

    // denominators (exact fp32)
    dpart_s[tid] = dpart;
    __syncthreads();
    if (tid < BM) {
        float s = 0.f;
        #pragma unroll
        for (int q = 0; q < TPR; q++) s += dpart_s[tid * TPR + q];
        inv_s[tid] = 1.f / s;
    }
    __syncthreads();

    // epilogue: normalize + ELU + store fp32
    const int g = lane >> 2, tig = lane & 3;
    #pragma unroll
    for (int mi = 0; mi < MI; mi++) {
        int rr0 = wm + mi * 16 + g;
        float inv0 = inv_s[rr0], inv1 = inv_s[rr0 + 8];
        #pragma unroll
        for (int f = 0; f < 2 * N16; f++) {
            int col = wn + f * 8 + tig * 2;
            float v0 = acc[mi][f][0] * inv0;
            float v1 = acc[mi][f][1] * inv0;
            float v2 = acc[mi][f][2] * inv1;
            float v3 = acc[mi][f][3] * inv1;
            v0 = (v0 > 0.f) ? v0 : expm1f(v0);
            v1 = (v1 > 0.f) ? v1 : expm1f(v1);
            v2 = (v2 > 0.f) ? v2 : expm1f(v2);
            v3 = (v3 > 0.f) ? v3 : expm1f(v3);
            if (LAYER == 1) {
                float* o0 = g_x2 + (size_t)(i0 + rr0) * (NH * FH) + h * FH + col;
                float* o1 = g_x2 + (size_t)(i0 + rr0 + 8) * (NH * FH) + h * FH + col;
                *(float2*)o0 = make_float2(v0, v1);
                *(float2*)o1 = make_float2(v2, v3);
            } else {
                float* o0 = dout + (size_t)(i0 + rr0) * FOUT + col;
                float* o1 = dout + (size_t)(i0 + rr0 + 8) * FOUT + col;
                *(float2*)o0 = make_float2(v0, v1);
                *(float2*)o1 = make_float2(v2, v3);
            }
        }
    }
}

// ---------------- final log_softmax over 64 cols, one warp per row ----------
__global__ void logsoftmax_kernel(float* __restrict__ out) {
    int gw   = (blockIdx.x * blockDim.x + threadIdx.x) >> 5;
    int lane = threadIdx.x & 31;
    if (gw >= GN) return;
    float* row = out + (size_t)gw * FOUT;
    float v0 = row[lane], v1 = row[lane + 32];
    float m = fmaxf(v0, v1);
    for (int o = 16; o; o >>= 1) m = fmaxf(m, __shfl_xor_sync(0xffffffffu, m, o));
    float s = __expf(v0 - m) + __expf(v1 - m);
    for (int o = 16; o; o >>= 1) s += __shfl_xor_sync(0xffffffffu, s, o);
    float lse = m + logf(s);
    row[lane] = v0 - lse;
    row[lane + 32] = v1 - lse;
}

// ---------------- launch ----------------------------------------------------
extern "C" void kernel_launch(void* const* d_in, const int* in_sizes, int n_in,
                              void* d_out, int out_size) {
    const float* features = (const float*)d_in[0];
    const int*   adj      = (const int*)d_in[1];
    const float* W1  = (const float*)d_in[2];
    const float* a1s = (const float*)d_in[3];
    const float* a1d = (const float*)d_in[4];
    const float* W2  = (const float*)d_in[5];
    const float* a2s = (const float*)d_in[6];
    const float* a2d = (const float*)d_in[7];
    float* out = (float*)d_out;

    const int SMEM1 = 2048 + 128 * 136 * 2 + 128 * 136 * 2;  // 71680
    const int SMEM2 = 2048 + 64 * 136 * 2 + 128 * 72 * 2;    // 37888
    cudaFuncSetAttribute(attn_mma_kernel<128, FH, 1>,
                         cudaFuncAttributeMaxDynamicSharedMemorySize, SMEM1);
    cudaFuncSetAttribute(attn_mma_kernel<64, FOUT, 2>,
                         cudaFuncAttributeMaxDynamicSharedMemorySize, SMEM2);

    pack_adj_kernel<<<(GN * GN) / 256, 256>>>(adj);

    // layer 1
    gemm_kernel<FIN, FH, 1><<<dim3(GN / 64, FH / 64, NH), 256>>>(features, W1);
    srcdst_kernel<FH, 1><<<(NH * GN) / 8, 256>>>(a1s, a1d);
    maxdst_kernel<1><<<NH, 256>>>();
    attn_mma_kernel<128, FH, 1><<<dim3(GN / 128, NH), 256, SMEM1>>>(nullptr);

    // layer 2
    gemm_kernel<NH * FH, FOUT, 2><<<dim3(GN / 64, 1, 1), 256>>>(nullptr, W2);
    srcdst_kernel<FOUT, 2><<<GN / 8, 256>>>(a2s, a2d);
    maxdst_kernel<2><<<1, 256>>>();
    attn_mma_kernel<64, FOUT, 2><<<dim3(GN / 64, 1), 256, SMEM2>>>(out);

    logsoftmax_kernel<<<GN / 8, 256>>>(out);
}

// round 11
// speedup vs baseline: 2.2254x; 1.2003x over previous
#include <cuda_runtime.h>
#include <cuda_fp16.h>
#include <cstdint>
#include <math.h>

#define GN   4096
#define FIN  512
#define FH   128
#define NH   4
#define FOUT 64
#define ALPHA 0.2f

// ---------------- scratch: EXACT same global set/sizes as the passing round --
__device__ __align__(16) float  g_h1[NH * GN * FH];   // fp32 H1; later aliased as fp16 x2h
__device__ float  g_h2[GN * FOUT];
__device__ __half g_h1h[NH * GN * FH];                // fp16 H1 (attn B operand)
__device__ __half g_h2h[GN * FOUT];
__device__ float  g_src1[NH * GN];
__device__ float  g_dst1[NH * GN];
__device__ float  g_src2[GN];
__device__ float  g_dst2[GN];
__device__ float  g_mdst[NH + 1];                     // ordered-uint encoded via casts
__device__ unsigned g_adj[GN * GN / 32];              // bit mask, 2 MB
__device__ __align__(16) float  g_x2[GN * (NH * FH)]; // aliased: feath | W1h | W2h

// half-aliased views (offsets in halfs; all 16B aligned)
#define FEATH ((__half*)g_x2)                          // 2,097,152 halfs
#define W1H   (((__half*)g_x2) + 2097152)              // 262,144 halfs
#define W2H   (((__half*)g_x2) + 2359296)              // 32,768 halfs
#define X2H   ((__half*)g_h1)                          // 2,097,152 halfs

// ---------------- PTX helpers ------------------------------------------------
__device__ __forceinline__ unsigned s2u(const void* p) {
    unsigned a;
    asm("{ .reg .u64 t; cvta.to.shared.u64 t, %1; cvt.u32.u64 %0, t; }"
        : "=r"(a) : "l"(p));
    return a;
}

__device__ __forceinline__ void ldsm4(unsigned* d, unsigned addr) {
    asm volatile("ldmatrix.sync.aligned.m8n8.x4.shared.b16 {%0,%1,%2,%3}, [%4];"
                 : "=r"(d[0]), "=r"(d[1]), "=r"(d[2]), "=r"(d[3]) : "r"(addr));
}

__device__ __forceinline__ void ldsm4t(unsigned* d, unsigned addr) {
    asm volatile("ldmatrix.sync.aligned.m8n8.x4.trans.shared.b16 {%0,%1,%2,%3}, [%4];"
                 : "=r"(d[0]), "=r"(d[1]), "=r"(d[2]), "=r"(d[3]) : "r"(addr));
}

__device__ __forceinline__ void mma16816(float* c, const unsigned* a,
                                         unsigned b0, unsigned b1) {
    asm volatile(
        "mma.sync.aligned.m16n8k16.row.col.f32.f16.f16.f32 "
        "{%0,%1,%2,%3}, {%4,%5,%6,%7}, {%8,%9}, {%0,%1,%2,%3};"
        : "+f"(c[0]), "+f"(c[1]), "+f"(c[2]), "+f"(c[3])
        : "r"(a[0]), "r"(a[1]), "r"(a[2]), "r"(a[3]), "r"(b0), "r"(b1));
}

// monotone float<->uint map for atomicMax on signed floats
__device__ __forceinline__ unsigned f2ord(float f) {
    unsigned u = __float_as_uint(f);
    return (u & 0x80000000u) ? ~u : (u | 0x80000000u);
}
__device__ __forceinline__ float ord2f(unsigned u) {
    return (u & 0x80000000u) ? __uint_as_float(u & 0x7fffffffu)
                             : __uint_as_float(~u);
}

// ---------------- pack: adjacency bits + fp16 conversions + mdst init -------
__global__ void pack_adj_kernel(const int* __restrict__ adj,
                                const float* __restrict__ features,
                                const float* __restrict__ W1,
                                const float* __restrict__ W2) {
    int bid = blockIdx.x, tid = threadIdx.x;
    int i = bid * 256 + tid;
    unsigned bal = __ballot_sync(0xffffffffu, adj[i] > 0);
    if ((tid & 31) == 0) g_adj[i >> 5] = bal;

    if (bid == 0 && tid <= NH) ((unsigned*)g_mdst)[tid] = 0u;  // ordered -inf
    if (bid < 8192) {
        FEATH[i] = __float2half(features[i]);
    } else if (bid < 8192 + 1024) {
        int k = (bid - 8192) * 256 + tid;
        W1H[k] = __float2half(W1[k]);
    } else if (bid < 8192 + 1024 + 128) {
        int k = (bid - 9216) * 256 + tid;
        W2H[k] = __float2half(W2[k]);
    }
}

// ---------------- HMMA GEMM: C[M,NC] = A[M,K](fp16) @ B[K,NC](fp16) ---------
// Single-buffered, phase-separated, static smem, no cp.async. Head = blockIdx.z.
// LAYER==1: A=FEATH, B=W1H(+head), C=g_h1, Ch=g_h1h. LAYER==2: A=X2H, B=W2H.
template<int K, int NC, int LAYER>
__global__ __launch_bounds__(256) void hgemm_kernel() {
    constexpr int BK = 64, NKT = K / BK;
    constexpr int ASTR = BK + 8;               // halfs
    constexpr int BSTR = NC + 8;
    constexpr int N16 = NC / 32;

    __shared__ __align__(16) __half a_s[128 * ASTR];
    __shared__ __align__(16) __half b_s[BK * BSTR];
    const unsigned a32 = s2u(a_s);
    const unsigned b32 = s2u(b_s);

    const int tid = threadIdx.x;
    const int r0 = blockIdx.x * 128;
    const __half* A  = (LAYER == 1) ? FEATH : X2H;
    const __half* Bm = ((LAYER == 1) ? W1H : W2H) + (size_t)blockIdx.z * K * NC;
    float*  C  = (LAYER == 1) ? (g_h1  + (size_t)blockIdx.z * GN * NC) : g_h2;
    __half* Ch = (LAYER == 1) ? (g_h1h + (size_t)blockIdx.z * GN * NC) : g_h2h;

    const int w = tid >> 5, lane = tid & 31;
    const int wm = (w & 3) * 32;
    const int wn = (w >> 2) * (NC / 2);

    float acc[2][2 * N16][4];
    #pragma unroll
    for (int a = 0; a < 2; a++)
        #pragma unroll
        for (int b = 0; b < 2 * N16; b++)
            #pragma unroll
            for (int c = 0; c < 4; c++) acc[a][b][c] = 0.f;

    for (int kt = 0; kt < NKT; kt++) {
        __syncthreads();
        {   // stage A tile: 128 x 64 halfs (uint4 chunks)
            #pragma unroll
            for (int q = 0; q < 4; q++) {
                int c = tid + q * 256;
                int row = c >> 3, ch = c & 7;
                uint4 v = *(const uint4*)&A[(size_t)(r0 + row) * K + kt * BK + ch * 8];
                *(uint4*)&a_s[row * ASTR + ch * 8] = v;
            }
        }
        {   // stage B tile: 64 x NC halfs
            #pragma unroll
            for (int q = 0; q < NC / 32; q++) {
                int c = tid + q * 256;
                int row = c / (NC / 8), ch = c % (NC / 8);
                uint4 v = *(const uint4*)&Bm[(size_t)(kt * BK + row) * NC + ch * 8];
                *(uint4*)&b_s[row * BSTR + ch * 8] = v;
            }
        }
        __syncthreads();
        #pragma unroll
        for (int k16 = 0; k16 < BK / 16; k16++) {
            unsigned afr[2][4];
            #pragma unroll
            for (int mi = 0; mi < 2; mi++)
                ldsm4(afr[mi], a32 +
                      ((wm + mi * 16 + (lane & 15)) * ASTR +
                       k16 * 16 + (lane >> 4) * 8) * 2);
            #pragma unroll
            for (int nj = 0; nj < N16; nj++) {
                unsigned bfr[4];
                ldsm4t(bfr, b32 +
                       ((k16 * 16 + (lane & 15)) * BSTR +
                        wn + nj * 16 + (lane >> 4) * 8) * 2);
                #pragma unroll
                for (int mi = 0; mi < 2; mi++) {
                    mma16816(acc[mi][2 * nj],     afr[mi], bfr[0], bfr[1]);
                    mma16816(acc[mi][2 * nj + 1], afr[mi], bfr[2], bfr[3]);
                }
            }
        }
    }

    const int g = lane >> 2, tig = lane & 3;
    #pragma unroll
    for (int mi = 0; mi < 2; mi++) {
        int rr0 = r0 + wm + mi * 16 + g;
        #pragma unroll
        for (int f = 0; f < 2 * N16; f++) {
            int col = wn + f * 8 + tig * 2;
            size_t i0 = (size_t)rr0 * NC + col;
            size_t i1 = (size_t)(rr0 + 8) * NC + col;
            *(float2*)&C[i0] = make_float2(acc[mi][f][0], acc[mi][f][1]);
            *(float2*)&C[i1] = make_float2(acc[mi][f][2], acc[mi][f][3]);
            *(__half2*)&Ch[i0] = __floats2half2_rn(acc[mi][f][0], acc[mi][f][1]);
            *(__half2*)&Ch[i1] = __floats2half2_rn(acc[mi][f][2], acc[mi][f][3]);
        }
    }
}

// ---------------- src/dst projections (+ fused atomic max of dst) -----------
template<int F, int LAYER>
__global__ void srcdst_kernel(const float* __restrict__ a_src,
                              const float* __restrict__ a_dst) {
    const float* Hm = (LAYER == 1) ? g_h1 : g_h2;
    float* so  = (LAYER == 1) ? g_src1 : g_src2;
    float* dso = (LAYER == 1) ? g_dst1 : g_dst2;
    int gw   = (blockIdx.x * blockDim.x + threadIdx.x) >> 5;
    int lane = threadIdx.x & 31;
    int hh = gw / GN;
    const float* row = Hm + (size_t)gw * F;
    float s = 0.f, d = 0.f;
    for (int c = lane; c < F; c += 32) {
        float v = row[c];
        s += v * a_src[hh * F + c];
        d += v * a_dst[hh * F + c];
    }
    for (int o = 16; o; o >>= 1) {
        s += __shfl_xor_sync(0xffffffffu, s, o);
        d += __shfl_xor_sync(0xffffffffu, d, o);
    }
    if (lane == 0) {
        so[gw] = s; dso[gw] = d;
        atomicMax(((unsigned*)g_mdst) + ((LAYER == 1) ? hh : NH), f2ord(d));
    }
}

// ---------------- fused masked-softmax attention (HMMA, round-4 structure) --
// LAYER==1 epilogue writes fp16 X2H (aliased over g_h1); LAYER==2 epilogue
// fuses log_softmax and writes dout.
template<int BM, int NB, int LAYER>
__global__ __launch_bounds__(256) void attn_mma_kernel(float* __restrict__ dout) {
    constexpr int KT  = 128;
    constexpr int TPR = 256 / BM;
    constexpr int JPT = KT / TPR;
    constexpr int WPT = JPT / 32;
    constexpr int WM  = BM / 4;
    constexpr int WN  = NB / 2;
    constexpr int MI  = WM / 16;
    constexpr int N16 = WN / 16;
    constexpr int PSTR = KT + 8;
    constexpr int HSTR = NB + 8;

    extern __shared__ __align__(16) char smem_c[];
    float* dpart_s = (float*)smem_c;
    float* inv_s   = (float*)(smem_c + 1024);
    char*  p_s     = smem_c + 2048;
    char*  h_s     = p_s + BM * PSTR * 2;

    const unsigned sbase = s2u(smem_c);
    const unsigned pb32  = sbase + 2048;
    const unsigned hb32  = pb32 + BM * PSTR * 2;

    const int tid = threadIdx.x;
    const int h   = blockIdx.y;
    const int i0  = blockIdx.x * BM;

    const float* srcv = (LAYER == 1) ? (g_src1 + (size_t)h * GN) : g_src2;
    const float* dstv = (LAYER == 1) ? (g_dst1 + (size_t)h * GN) : g_dst2;
    const __half* Hh  = (LAYER == 1) ? (g_h1h + (size_t)h * GN * FH) : g_h2h;
    const float md = ord2f(((unsigned*)g_mdst)[(LAYER == 1) ? h : NH]);

    const int r   = tid / TPR;
    const int sub = tid % TPR;
    const float srcr = srcv[i0 + r];
    float t0 = srcr + md;
    const float mrow = (t0 > 0.f) ? t0 : (ALPHA * t0);   // >= true row max
    const unsigned* adjR = g_adj + (size_t)(i0 + r) * (GN / 32);
    float dpart = 0.f;

    const int w = tid >> 5, lane = tid & 31;
    const int wm = (w & 3) * WM;
    const int wn = (w >> 2) * WN;
    float acc[MI][2 * N16][4];
    #pragma unroll
    for (int a = 0; a < MI; a++)
        #pragma unroll
        for (int b = 0; b < 2 * N16; b++)
            #pragma unroll
            for (int c = 0; c < 4; c++) acc[a][b][c] = 0.f;

    for (int jt = 0; jt < GN / KT; jt++) {
        const int j0 = jt * KT;
        __syncthreads();
        {   // phase 1: P tile
            unsigned aw[WPT];
            #pragma unroll
            for (int q = 0; q < WPT; q++)
                aw[q] = __ldg(adjR + jt * (KT / 32) + sub * WPT + q);
            const float* dstp = dstv + j0 + sub * JPT;
            char* prow = p_s + r * (PSTR * 2) + sub * JPT * 2;
            #pragma unroll 4
            for (int kk = 0; kk < JPT / 2; kk++) {
                float2 dv = *(const float2*)(dstp + 2 * kk);
                float e0 = srcr + dv.x; e0 = (e0 > 0.f) ? e0 : (ALPHA * e0);
                float e1 = srcr + dv.y; e1 = (e1 > 0.f) ? e1 : (ALPHA * e1);
                unsigned wsel = aw[kk >> 4];
                int sh = (2 * kk) & 31;
                float p0 = ((wsel >> sh) & 1u)       ? __expf(e0 - mrow) : 0.f;
                float p1 = ((wsel >> (sh + 1)) & 1u) ? __expf(e1 - mrow) : 0.f;
                dpart += p0 + p1;
                *(__half2*)(prow + 4 * kk) = __floats2half2_rn(p0, p1);
            }
        }
        {   // phase 1b: H tile
            for (int c = tid; c < KT * NB / 8; c += 256) {
                int row = c / (NB / 8), ch = c % (NB / 8);
                uint4 v = *(const uint4*)(Hh + (size_t)(j0 + row) * NB + ch * 8);
                *(uint4*)(h_s + row * (HSTR * 2) + ch * 16) = v;
            }
        }
        __syncthreads();
        {   // phase 2: MMAs
            #pragma unroll
            for (int k16 = 0; k16 < KT / 16; k16++) {
                unsigned afr[MI][4];
                #pragma unroll
                for (int mi = 0; mi < MI; mi++)
                    ldsm4(afr[mi], pb32 +
                          ((wm + mi * 16 + (lane & 15)) * PSTR +
                           k16 * 16 + (lane >> 4) * 8) * 2);
                #pragma unroll
                for (int nj = 0; nj < N16; nj++) {
                    unsigned bfr[4];
                    ldsm4t(bfr, hb32 +
                           ((k16 * 16 + (lane & 15)) * HSTR +
                            wn + nj * 16 + (lane >> 4) * 8) * 2);
                    #pragma unroll
                    for (int mi = 0; mi < MI; mi++) {
                        mma16816(acc[mi][2 * nj],     afr[mi], bfr[0], bfr[1]);
                        mma16816(acc[mi][2 * nj + 1], afr[mi], bfr[2], bfr[3]);
                    }
                }
            }
        }
    }

    // exact fp32 denominators
    dpart_s[tid] = dpart;
    __syncthreads();
    if (tid < BM) {
        float s = 0.f;
        #pragma unroll
        for (int q = 0; q < TPR; q++) s += dpart_s[tid * TPR + q];
        inv_s[tid] = 1.f / s;
    }
    __syncthreads();

    const int g = lane >> 2, tig = lane & 3;
    if (LAYER == 1) {
        #pragma unroll
        for (int mi = 0; mi < MI; mi++) {
            int rr0 = wm + mi * 16 + g;
            float inv0 = inv_s[rr0], inv1 = inv_s[rr0 + 8];
            #pragma unroll
            for (int f = 0; f < 2 * N16; f++) {
                int col = wn + f * 8 + tig * 2;
                float v0 = acc[mi][f][0] * inv0;
                float v1 = acc[mi][f][1] * inv0;
                float v2 = acc[mi][f][2] * inv1;
                float v3 = acc[mi][f][3] * inv1;
                v0 = (v0 > 0.f) ? v0 : expm1f(v0);
                v1 = (v1 > 0.f) ? v1 : expm1f(v1);
                v2 = (v2 > 0.f) ? v2 : expm1f(v2);
                v3 = (v3 > 0.f) ? v3 : expm1f(v3);
                size_t o0 = (size_t)(i0 + rr0) * (NH * FH) + h * FH + col;
                size_t o1 = (size_t)(i0 + rr0 + 8) * (NH * FH) + h * FH + col;
                *(__half2*)&X2H[o0] = __floats2half2_rn(v0, v1);
                *(__half2*)&X2H[o1] = __floats2half2_rn(v2, v3);
            }
        }
    } else {
        // normalize + ELU -> smem, then fused log_softmax -> dout
        float* ox = (float*)(smem_c + 2048);          // [BM][68], reuses P
        #pragma unroll
        for (int f = 0; f < 2 * N16; f++) {
            int rr0 = wm + g;
            float inv0 = inv_s[rr0], inv1 = inv_s[rr0 + 8];
            int col = wn + f * 8 + tig * 2;
            float v0 = acc[0][f][0] * inv0;
            float v1 = acc[0][f][1] * inv0;
            float v2 = acc[0][f][2] * inv1;
            float v3 = acc[0][f][3] * inv1;
            v0 = (v0 > 0.f) ? v0 : expm1f(v0);
            v1 = (v1 > 0.f) ? v1 : expm1f(v1);
            v2 = (v2 > 0.f) ? v2 : expm1f(v2);
            v3 = (v3 > 0.f) ? v3 : expm1f(v3);
            ox[rr0 * 68 + col]           = v0;
            ox[rr0 * 68 + col + 1]       = v1;
            ox[(rr0 + 8) * 68 + col]     = v2;
            ox[(rr0 + 8) * 68 + col + 1] = v3;
        }
        __syncthreads();
        #pragma unroll
        for (int rr = w * 8; rr < w * 8 + 8; rr++) {
            float v0 = ox[rr * 68 + lane];
            float v1 = ox[rr * 68 + lane + 32];
            float m = fmaxf(v0, v1);
            #pragma unroll
            for (int o = 16; o; o >>= 1)
                m = fmaxf(m, __shfl_xor_sync(0xffffffffu, m, o));
            float s = __expf(v0 - m) + __expf(v1 - m);
            #pragma unroll
            for (int o = 16; o; o >>= 1)
                s += __shfl_xor_sync(0xffffffffu, s, o);
            float lse = m + logf(s);
            dout[(size_t)(i0 + rr) * FOUT + lane]      = v0 - lse;
            dout[(size_t)(i0 + rr) * FOUT + lane + 32] = v1 - lse;
        }
    }
}

// ---------------- launch ----------------------------------------------------
extern "C" void kernel_launch(void* const* d_in, const int* in_sizes, int n_in,
                              void* d_out, int out_size) {
    const float* features = (const float*)d_in[0];
    const int*   adj      = (const int*)d_in[1];
    const float* W1  = (const float*)d_in[2];
    const float* a1s = (const float*)d_in[3];
    const float* a1d = (const float*)d_in[4];
    const float* W2  = (const float*)d_in[5];
    const float* a2s = (const float*)d_in[6];
    const float* a2d = (const float*)d_in[7];
    float* out = (float*)d_out;

    const int SMEM1 = 2048 + 128 * 136 * 2 + 128 * 136 * 2;  // 71680
    const int SMEM2 = 2048 + 64 * 136 * 2 + 128 * 72 * 2;    // 37888
    cudaFuncSetAttribute(attn_mma_kernel<128, FH, 1>,
                         cudaFuncAttributeMaxDynamicSharedMemorySize, SMEM1);
    cudaFuncSetAttribute(attn_mma_kernel<64, FOUT, 2>,
                         cudaFuncAttributeMaxDynamicSharedMemorySize, SMEM2);

    pack_adj_kernel<<<(GN * GN) / 256, 256>>>(adj, features, W1, W2);

    // layer 1
    hgemm_kernel<FIN, FH, 1><<<dim3(GN / 128, 1, NH), 256>>>();
    srcdst_kernel<FH, 1><<<(NH * GN) / 8, 256>>>(a1s, a1d);
    attn_mma_kernel<128, FH, 1><<<dim3(GN / 128, NH), 256, SMEM1>>>(nullptr);

    // layer 2
    hgemm_kernel<NH * FH, FOUT, 2><<<dim3(GN / 128, 1, 1), 256>>>();
    srcdst_kernel<FOUT, 2><<<GN / 8, 256>>>(a2s, a2d);
    attn_mma_kernel<64, FOUT, 2><<<dim3(GN / 64, 1), 256, SMEM2>>>(out);
}

// round 12
// speedup vs baseline: 3.3029x; 1.4841x over previous
#include <cuda_runtime.h>
#include <cuda_fp16.h>
#include <cstdint>
#include <math.h>

#define GN   4096
#define FIN  512
#define FH   128
#define NH   4
#define FOUT 64
#define ALPHA 0.2f

// ---------------- scratch: EXACT same global set/sizes as the passing round --
__device__ __align__(16) float  g_h1[NH * GN * FH];   // fp32 H1; later aliased as fp16 x2h
__device__ float  g_h2[GN * FOUT];
__device__ __half g_h1h[NH * GN * FH];                // fp16 H1 (attn B operand)
__device__ __half g_h2h[GN * FOUT];
__device__ float  g_src1[NH * GN];
__device__ float  g_dst1[NH * GN];
__device__ float  g_src2[GN];
__device__ float  g_dst2[GN];
__device__ float  g_mdst[NH + 1];                     // ordered-uint encoded via casts
__device__ unsigned g_adj[GN * GN / 32];              // bit mask, 2 MB
__device__ __align__(16) float  g_x2[GN * (NH * FH)]; // aliased: feath|W1h|W2h, then attn2 partials

// half-aliased views (offsets in halfs; all 16B aligned)
#define FEATH ((__half*)g_x2)                          // 2,097,152 halfs
#define W1H   (((__half*)g_x2) + 2097152)              // 262,144 halfs
#define W2H   (((__half*)g_x2) + 2359296)              // 32,768 halfs
#define X2H   ((__half*)g_h1)                          // 2,097,152 halfs
// attn2 partial buffers (g_x2 is dead by attn2 time)
#define PNUM  ((float*)g_x2)                           // [4][GN][FOUT] = 4 MB
#define PDEN  (((float*)g_x2) + 1048576)               // [4][GN]

// ---------------- PTX helpers ------------------------------------------------
__device__ __forceinline__ unsigned s2u(const void* p) {
    unsigned a;
    asm("{ .reg .u64 t; cvta.to.shared.u64 t, %1; cvt.u32.u64 %0, t; }"
        : "=r"(a) : "l"(p));
    return a;
}

__device__ __forceinline__ void ldsm4(unsigned* d, unsigned addr) {
    asm volatile("ldmatrix.sync.aligned.m8n8.x4.shared.b16 {%0,%1,%2,%3}, [%4];"
                 : "=r"(d[0]), "=r"(d[1]), "=r"(d[2]), "=r"(d[3]) : "r"(addr));
}

__device__ __forceinline__ void ldsm4t(unsigned* d, unsigned addr) {
    asm volatile("ldmatrix.sync.aligned.m8n8.x4.trans.shared.b16 {%0,%1,%2,%3}, [%4];"
                 : "=r"(d[0]), "=r"(d[1]), "=r"(d[2]), "=r"(d[3]) : "r"(addr));
}

__device__ __forceinline__ void mma16816(float* c, const unsigned* a,
                                         unsigned b0, unsigned b1) {
    asm volatile(
        "mma.sync.aligned.m16n8k16.row.col.f32.f16.f16.f32 "
        "{%0,%1,%2,%3}, {%4,%5,%6,%7}, {%8,%9}, {%0,%1,%2,%3};"
        : "+f"(c[0]), "+f"(c[1]), "+f"(c[2]), "+f"(c[3])
        : "r"(a[0]), "r"(a[1]), "r"(a[2]), "r"(a[3]), "r"(b0), "r"(b1));
}

// monotone float<->uint map for atomicMax on signed floats
__device__ __forceinline__ unsigned f2ord(float f) {
    unsigned u = __float_as_uint(f);
    return (u & 0x80000000u) ? ~u : (u | 0x80000000u);
}
__device__ __forceinline__ float ord2f(unsigned u) {
    return (u & 0x80000000u) ? __uint_as_float(u & 0x7fffffffu)
                             : __uint_as_float(~u);
}

// ---------------- pack: adjacency bits + fp16 conversions + mdst init -------
__global__ void pack_adj_kernel(const int* __restrict__ adj,
                                const float* __restrict__ features,
                                const float* __restrict__ W1,
                                const float* __restrict__ W2) {
    int bid = blockIdx.x, tid = threadIdx.x;
    int i = bid * 256 + tid;
    unsigned bal = __ballot_sync(0xffffffffu, adj[i] > 0);
    if ((tid & 31) == 0) g_adj[i >> 5] = bal;

    if (bid == 0 && tid <= NH) ((unsigned*)g_mdst)[tid] = 0u;  // ordered -inf
    if (bid < 8192) {
        FEATH[i] = __float2half(features[i]);
    } else if (bid < 8192 + 1024) {
        int k = (bid - 8192) * 256 + tid;
        W1H[k] = __float2half(W1[k]);
    } else if (bid < 8192 + 1024 + 128) {
        int k = (bid - 9216) * 256 + tid;
        W2H[k] = __float2half(W2[k]);
    }
}

// ---------------- HMMA GEMM: C[M,NC] = A[M,K](fp16) @ B[K,NC](fp16) ---------
// Single-buffered, phase-separated, static smem, no cp.async. Head = blockIdx.z.
template<int K, int NC, int LAYER>
__global__ __launch_bounds__(256) void hgemm_kernel() {
    constexpr int BK = 64, NKT = K / BK;
    constexpr int ASTR = BK + 8;               // halfs
    constexpr int BSTR = NC + 8;
    constexpr int N16 = NC / 32;

    __shared__ __align__(16) __half a_s[128 * ASTR];
    __shared__ __align__(16) __half b_s[BK * BSTR];
    const unsigned a32 = s2u(a_s);
    const unsigned b32 = s2u(b_s);

    const int tid = threadIdx.x;
    const int r0 = blockIdx.x * 128;
    const __half* A  = (LAYER == 1) ? FEATH : X2H;
    const __half* Bm = ((LAYER == 1) ? W1H : W2H) + (size_t)blockIdx.z * K * NC;
    float*  C  = (LAYER == 1) ? (g_h1  + (size_t)blockIdx.z * GN * NC) : g_h2;
    __half* Ch = (LAYER == 1) ? (g_h1h + (size_t)blockIdx.z * GN * NC) : g_h2h;

    const int w = tid >> 5, lane = tid & 31;
    const int wm = (w & 3) * 32;
    const int wn = (w >> 2) * (NC / 2);

    float acc[2][2 * N16][4];
    #pragma unroll
    for (int a = 0; a < 2; a++)
        #pragma unroll
        for (int b = 0; b < 2 * N16; b++)
            #pragma unroll
            for (int c = 0; c < 4; c++) acc[a][b][c] = 0.f;

    for (int kt = 0; kt < NKT; kt++) {
        __syncthreads();
        {   // stage A tile: 128 x 64 halfs (uint4 chunks)
            #pragma unroll
            for (int q = 0; q < 4; q++) {
                int c = tid + q * 256;
                int row = c >> 3, ch = c & 7;
                uint4 v = *(const uint4*)&A[(size_t)(r0 + row) * K + kt * BK + ch * 8];
                *(uint4*)&a_s[row * ASTR + ch * 8] = v;
            }
        }
        {   // stage B tile: 64 x NC halfs
            #pragma unroll
            for (int q = 0; q < NC / 32; q++) {
                int c = tid + q * 256;
                int row = c / (NC / 8), ch = c % (NC / 8);
                uint4 v = *(const uint4*)&Bm[(size_t)(kt * BK + row) * NC + ch * 8];
                *(uint4*)&b_s[row * BSTR + ch * 8] = v;
            }
        }
        __syncthreads();
        #pragma unroll
        for (int k16 = 0; k16 < BK / 16; k16++) {
            unsigned afr[2][4];
            #pragma unroll
            for (int mi = 0; mi < 2; mi++)
                ldsm4(afr[mi], a32 +
                      ((wm + mi * 16 + (lane & 15)) * ASTR +
                       k16 * 16 + (lane >> 4) * 8) * 2);
            #pragma unroll
            for (int nj = 0; nj < N16; nj++) {
                unsigned bfr[4];
                ldsm4t(bfr, b32 +
                       ((k16 * 16 + (lane & 15)) * BSTR +
                        wn + nj * 16 + (lane >> 4) * 8) * 2);
                #pragma unroll
                for (int mi = 0; mi < 2; mi++) {
                    mma16816(acc[mi][2 * nj],     afr[mi], bfr[0], bfr[1]);
                    mma16816(acc[mi][2 * nj + 1], afr[mi], bfr[2], bfr[3]);
                }
            }
        }
    }

    const int g = lane >> 2, tig = lane & 3;
    #pragma unroll
    for (int mi = 0; mi < 2; mi++) {
        int rr0 = r0 + wm + mi * 16 + g;
        #pragma unroll
        for (int f = 0; f < 2 * N16; f++) {
            int col = wn + f * 8 + tig * 2;
            size_t i0 = (size_t)rr0 * NC + col;
            size_t i1 = (size_t)(rr0 + 8) * NC + col;
            *(float2*)&C[i0] = make_float2(acc[mi][f][0], acc[mi][f][1]);
            *(float2*)&C[i1] = make_float2(acc[mi][f][2], acc[mi][f][3]);
            *(__half2*)&Ch[i0] = __floats2half2_rn(acc[mi][f][0], acc[mi][f][1]);
            *(__half2*)&Ch[i1] = __floats2half2_rn(acc[mi][f][2], acc[mi][f][3]);
        }
    }
}

// ---------------- src/dst projections (+ fused atomic max of dst) -----------
template<int F, int LAYER>
__global__ void srcdst_kernel(const float* __restrict__ a_src,
                              const float* __restrict__ a_dst) {
    const float* Hm = (LAYER == 1) ? g_h1 : g_h2;
    float* so  = (LAYER == 1) ? g_src1 : g_src2;
    float* dso = (LAYER == 1) ? g_dst1 : g_dst2;
    int gw   = (blockIdx.x * blockDim.x + threadIdx.x) >> 5;
    int lane = threadIdx.x & 31;
    int hh = gw / GN;
    const float* row = Hm + (size_t)gw * F;
    float s = 0.f, d = 0.f;
    for (int c = lane; c < F; c += 32) {
        float v = row[c];
        s += v * a_src[hh * F + c];
        d += v * a_dst[hh * F + c];
    }
    for (int o = 16; o; o >>= 1) {
        s += __shfl_xor_sync(0xffffffffu, s, o);
        d += __shfl_xor_sync(0xffffffffu, d, o);
    }
    if (lane == 0) {
        so[gw] = s; dso[gw] = d;
        atomicMax(((unsigned*)g_mdst) + ((LAYER == 1) ? hh : NH), f2ord(d));
    }
}

// ---------------- fused masked-softmax attention (HMMA) ---------------------
// LAYER==1 (JSPLIT=1): full j-range, epilogue writes fp16 X2H.
// LAYER==2 (JSPLIT=4): blockIdx.z selects a j-quarter; epilogue writes raw
// fp32 partial numerators (PNUM) + partial denominators (PDEN).
template<int BM, int NB, int LAYER, int JSPLIT>
__global__ __launch_bounds__(256, 2) void attn_mma_kernel(float* __restrict__ dout) {
    constexpr int KT  = 128;
    constexpr int NTS = (GN / KT) / JSPLIT;
    constexpr int TPR = 256 / BM;
    constexpr int JPT = KT / TPR;
    constexpr int WPT = JPT / 32;
    constexpr int WM  = BM / 4;
    constexpr int WN  = NB / 2;
    constexpr int MI  = WM / 16;
    constexpr int N16 = WN / 16;
    constexpr int PSTR = KT + 8;
    constexpr int HSTR = NB + 8;

    extern __shared__ __align__(16) char smem_c[];
    float* dpart_s = (float*)smem_c;
    float* inv_s   = (float*)(smem_c + 1024);
    char*  p_s     = smem_c + 2048;
    char*  h_s     = p_s + BM * PSTR * 2;

    const unsigned sbase = s2u(smem_c);
    const unsigned pb32  = sbase + 2048;
    const unsigned hb32  = pb32 + BM * PSTR * 2;

    const int tid = threadIdx.x;
    const int h   = blockIdx.y;
    const int i0  = blockIdx.x * BM;
    const int js  = (JSPLIT > 1) ? blockIdx.z : 0;

    const float* srcv = (LAYER == 1) ? (g_src1 + (size_t)h * GN) : g_src2;
    const float* dstv = (LAYER == 1) ? (g_dst1 + (size_t)h * GN) : g_dst2;
    const __half* Hh  = (LAYER == 1) ? (g_h1h + (size_t)h * GN * FH) : g_h2h;
    const float md = ord2f(((unsigned*)g_mdst)[(LAYER == 1) ? h : NH]);

    const int r   = tid / TPR;
    const int sub = tid % TPR;
    const float srcr = srcv[i0 + r];
    float t0 = srcr + md;
    const float mrow = (t0 > 0.f) ? t0 : (ALPHA * t0);   // >= true row max
    const unsigned* adjR = g_adj + (size_t)(i0 + r) * (GN / 32);
    float dpart = 0.f;

    const int w = tid >> 5, lane = tid & 31;
    const int wm = (w & 3) * WM;
    const int wn = (w >> 2) * WN;
    float acc[MI][2 * N16][4];
    #pragma unroll
    for (int a = 0; a < MI; a++)
        #pragma unroll
        for (int b = 0; b < 2 * N16; b++)
            #pragma unroll
            for (int c = 0; c < 4; c++) acc[a][b][c] = 0.f;

    for (int jt = js * NTS; jt < (js + 1) * NTS; jt++) {
        const int j0 = jt * KT;
        __syncthreads();
        {   // phase 1: P tile
            unsigned aw[WPT];
            #pragma unroll
            for (int q = 0; q < WPT; q++)
                aw[q] = __ldg(adjR + jt * (KT / 32) + sub * WPT + q);
            const float* dstp = dstv + j0 + sub * JPT;
            char* prow = p_s + r * (PSTR * 2) + sub * JPT * 2;
            #pragma unroll 4
            for (int kk = 0; kk < JPT / 2; kk++) {
                float2 dv = *(const float2*)(dstp + 2 * kk);
                float e0 = srcr + dv.x; e0 = (e0 > 0.f) ? e0 : (ALPHA * e0);
                float e1 = srcr + dv.y; e1 = (e1 > 0.f) ? e1 : (ALPHA * e1);
                unsigned wsel = aw[kk >> 4];
                int sh = (2 * kk) & 31;
                float p0 = ((wsel >> sh) & 1u)       ? __expf(e0 - mrow) : 0.f;
                float p1 = ((wsel >> (sh + 1)) & 1u) ? __expf(e1 - mrow) : 0.f;
                dpart += p0 + p1;
                *(__half2*)(prow + 4 * kk) = __floats2half2_rn(p0, p1);
            }
        }
        {   // phase 1b: H tile
            for (int c = tid; c < KT * NB / 8; c += 256) {
                int row = c / (NB / 8), ch = c % (NB / 8);
                uint4 v = *(const uint4*)(Hh + (size_t)(j0 + row) * NB + ch * 8);
                *(uint4*)(h_s + row * (HSTR * 2) + ch * 16) = v;
            }
        }
        __syncthreads();
        {   // phase 2: MMAs
            #pragma unroll
            for (int k16 = 0; k16 < KT / 16; k16++) {
                unsigned afr[MI][4];
                #pragma unroll
                for (int mi = 0; mi < MI; mi++)
                    ldsm4(afr[mi], pb32 +
                          ((wm + mi * 16 + (lane & 15)) * PSTR +
                           k16 * 16 + (lane >> 4) * 8) * 2);
                #pragma unroll
                for (int nj = 0; nj < N16; nj++) {
                    unsigned bfr[4];
                    ldsm4t(bfr, hb32 +
                           ((k16 * 16 + (lane & 15)) * HSTR +
                            wn + nj * 16 + (lane >> 4) * 8) * 2);
                    #pragma unroll
                    for (int mi = 0; mi < MI; mi++) {
                        mma16816(acc[mi][2 * nj],     afr[mi], bfr[0], bfr[1]);
                        mma16816(acc[mi][2 * nj + 1], afr[mi], bfr[2], bfr[3]);
                    }
                }
            }
        }
    }

    // denominators (exact fp32): full inverse (L1) or partial sum (L2)
    dpart_s[tid] = dpart;
    __syncthreads();
    if (tid < BM) {
        float s = 0.f;
        #pragma unroll
        for (int q = 0; q < TPR; q++) s += dpart_s[tid * TPR + q];
        if (LAYER == 1) inv_s[tid] = 1.f / s;
        else            PDEN[js * GN + i0 + tid] = s;
    }
    __syncthreads();

    const int g = lane >> 2, tig = lane & 3;
    if (LAYER == 1) {
        #pragma unroll
        for (int mi = 0; mi < MI; mi++) {
            int rr0 = wm + mi * 16 + g;
            float inv0 = inv_s[rr0], inv1 = inv_s[rr0 + 8];
            #pragma unroll
            for (int f = 0; f < 2 * N16; f++) {
                int col = wn + f * 8 + tig * 2;
                float v0 = acc[mi][f][0] * inv0;
                float v1 = acc[mi][f][1] * inv0;
                float v2 = acc[mi][f][2] * inv1;
                float v3 = acc[mi][f][3] * inv1;
                v0 = (v0 > 0.f) ? v0 : expm1f(v0);
                v1 = (v1 > 0.f) ? v1 : expm1f(v1);
                v2 = (v2 > 0.f) ? v2 : expm1f(v2);
                v3 = (v3 > 0.f) ? v3 : expm1f(v3);
                size_t o0 = (size_t)(i0 + rr0) * (NH * FH) + h * FH + col;
                size_t o1 = (size_t)(i0 + rr0 + 8) * (NH * FH) + h * FH + col;
                *(__half2*)&X2H[o0] = __floats2half2_rn(v0, v1);
                *(__half2*)&X2H[o1] = __floats2half2_rn(v2, v3);
            }
        }
    } else {
        // raw partial numerators -> PNUM[js]
        int rr0 = wm + g;
        #pragma unroll
        for (int f = 0; f < 2 * N16; f++) {
            int col = wn + f * 8 + tig * 2;
            float* o0 = PNUM + (size_t)js * GN * FOUT + (size_t)(i0 + rr0) * FOUT + col;
            float* o1 = PNUM + (size_t)js * GN * FOUT + (size_t)(i0 + rr0 + 8) * FOUT + col;
            *(float2*)o0 = make_float2(acc[0][f][0], acc[0][f][1]);
            *(float2*)o1 = make_float2(acc[0][f][2], acc[0][f][3]);
        }
    }
}

// ---------------- combine: sum partials, normalize, ELU, log_softmax --------
__global__ void combine_kernel(float* __restrict__ out) {
    int gw   = (blockIdx.x * blockDim.x + threadIdx.x) >> 5;   // row
    int lane = threadIdx.x & 31;
    float den = 0.f;
    #pragma unroll
    for (int js = 0; js < 4; js++) den += PDEN[js * GN + gw];
    float inv = 1.f / den;
    float v0 = 0.f, v1 = 0.f;
    #pragma unroll
    for (int js = 0; js < 4; js++) {
        const float* p = PNUM + (size_t)js * GN * FOUT + (size_t)gw * FOUT;
        v0 += p[lane];
        v1 += p[lane + 32];
    }
    v0 *= inv; v1 *= inv;
    v0 = (v0 > 0.f) ? v0 : expm1f(v0);
    v1 = (v1 > 0.f) ? v1 : expm1f(v1);
    float m = fmaxf(v0, v1);
    #pragma unroll
    for (int o = 16; o; o >>= 1) m = fmaxf(m, __shfl_xor_sync(0xffffffffu, m, o));
    float s = __expf(v0 - m) + __expf(v1 - m);
    #pragma unroll
    for (int o = 16; o; o >>= 1) s += __shfl_xor_sync(0xffffffffu, s, o);
    float lse = m + logf(s);
    out[(size_t)gw * FOUT + lane]      = v0 - lse;
    out[(size_t)gw * FOUT + lane + 32] = v1 - lse;
}

// ---------------- launch ----------------------------------------------------
extern "C" void kernel_launch(void* const* d_in, const int* in_sizes, int n_in,
                              void* d_out, int out_size) {
    const float* features = (const float*)d_in[0];
    const int*   adj      = (const int*)d_in[1];
    const float* W1  = (const float*)d_in[2];
    const float* a1s = (const float*)d_in[3];
    const float* a1d = (const float*)d_in[4];
    const float* W2  = (const float*)d_in[5];
    const float* a2s = (const float*)d_in[6];
    const float* a2d = (const float*)d_in[7];
    float* out = (float*)d_out;

    const int SMEM1 = 2048 + 64 * 136 * 2 + 128 * 136 * 2;   // 54272
    const int SMEM2 = 2048 + 64 * 136 * 2 + 128 * 72 * 2;    // 37888
    cudaFuncSetAttribute(attn_mma_kernel<64, FH, 1, 1>,
                         cudaFuncAttributeMaxDynamicSharedMemorySize, SMEM1);
    cudaFuncSetAttribute(attn_mma_kernel<64, FOUT, 2, 4>,
                         cudaFuncAttributeMaxDynamicSharedMemorySize, SMEM2);

    pack_adj_kernel<<<(GN * GN) / 256, 256>>>(adj, features, W1, W2);

    // layer 1
    hgemm_kernel<FIN, FH, 1><<<dim3(GN / 128, 1, NH), 256>>>();
    srcdst_kernel<FH, 1><<<(NH * GN) / 8, 256>>>(a1s, a1d);
    attn_mma_kernel<64, FH, 1, 1><<<dim3(GN / 64, NH, 1), 256, SMEM1>>>(nullptr);

    // layer 2
    hgemm_kernel<NH * FH, FOUT, 2><<<dim3(GN / 128, 1, 1), 256>>>();
    srcdst_kernel<FOUT, 2><<<GN / 8, 256>>>(a2s, a2d);
    attn_mma_kernel<64, FOUT, 2, 4><<<dim3(GN / 64, 1, 4), 256, SMEM2>>>(nullptr);
    combine_kernel<<<GN / 8, 256>>>(out);
}

// round 13
// speedup vs baseline: 4.1226x; 1.2482x over previous
#include <cuda_runtime.h>
#include <cuda_fp16.h>
#include <cstdint>
#include <math.h>

#define GN   4096
#define FIN  512
#define FH   128
#define NH   4
#define FOUT 64
#define ALPHA 0.2f

// ---------------- scratch: EXACT same global set/sizes as the passing round --
__device__ __align__(16) float  g_h1[NH * GN * FH];   // fp32 H1; later aliased as fp16 x2h
__device__ float  g_h2[GN * FOUT];
__device__ __half g_h1h[NH * GN * FH];                // fp16 H1 (attn B operand)
__device__ __half g_h2h[GN * FOUT];
__device__ float  g_src1[NH * GN];
__device__ float  g_dst1[NH * GN];
__device__ float  g_src2[GN];
__device__ float  g_dst2[GN];
__device__ float  g_mdst[NH + 1];                     // ordered-uint encoded via casts
__device__ unsigned g_adj[GN * GN / 32];              // bit mask, 2 MB
__device__ __align__(16) float  g_x2[GN * (NH * FH)]; // aliased: feath|W1h|W2h, then attn2 partials

// half-aliased views (offsets in halfs; all 16B aligned)
#define FEATH ((__half*)g_x2)                          // 2,097,152 halfs
#define W1H   (((__half*)g_x2) + 2097152)              // 262,144 halfs
#define W2H   (((__half*)g_x2) + 2359296)              // 32,768 halfs
#define X2H   ((__half*)g_h1)                          // 2,097,152 halfs
// attn2 partial buffers (g_x2 is dead by attn2 time)
#define PNUM  ((float*)g_x2)                           // [4][GN][FOUT] = 4 MB
#define PDEN  (((float*)g_x2) + 1048576)               // [4][GN]

// ---------------- PTX helpers ------------------------------------------------
__device__ __forceinline__ unsigned s2u(const void* p) {
    unsigned a;
    asm("{ .reg .u64 t; cvta.to.shared.u64 t, %1; cvt.u32.u64 %0, t; }"
        : "=r"(a) : "l"(p));
    return a;
}

__device__ __forceinline__ void ldsm4(unsigned* d, unsigned addr) {
    asm volatile("ldmatrix.sync.aligned.m8n8.x4.shared.b16 {%0,%1,%2,%3}, [%4];"
                 : "=r"(d[0]), "=r"(d[1]), "=r"(d[2]), "=r"(d[3]) : "r"(addr));
}

__device__ __forceinline__ void ldsm4t(unsigned* d, unsigned addr) {
    asm volatile("ldmatrix.sync.aligned.m8n8.x4.trans.shared.b16 {%0,%1,%2,%3}, [%4];"
                 : "=r"(d[0]), "=r"(d[1]), "=r"(d[2]), "=r"(d[3]) : "r"(addr));
}

__device__ __forceinline__ void mma16816(float* c, const unsigned* a,
                                         unsigned b0, unsigned b1) {
    asm volatile(
        "mma.sync.aligned.m16n8k16.row.col.f32.f16.f16.f32 "
        "{%0,%1,%2,%3}, {%4,%5,%6,%7}, {%8,%9}, {%0,%1,%2,%3};"
        : "+f"(c[0]), "+f"(c[1]), "+f"(c[2]), "+f"(c[3])
        : "r"(a[0]), "r"(a[1]), "r"(a[2]), "r"(a[3]), "r"(b0), "r"(b1));
}

__device__ __forceinline__ unsigned h2u(float a, float b) {
    __half2 h = __floats2half2_rn(a, b);
    return *reinterpret_cast<unsigned*>(&h);
}

// monotone float<->uint map for atomicMax on signed floats
__device__ __forceinline__ unsigned f2ord(float f) {
    unsigned u = __float_as_uint(f);
    return (u & 0x80000000u) ? ~u : (u | 0x80000000u);
}
__device__ __forceinline__ float ord2f(unsigned u) {
    return (u & 0x80000000u) ? __uint_as_float(u & 0x7fffffffu)
                             : __uint_as_float(~u);
}

// ---------------- pack: adjacency bits + fp16 conversions + mdst init -------
__global__ void pack_adj_kernel(const int* __restrict__ adj,
                                const float* __restrict__ features,
                                const float* __restrict__ W1,
                                const float* __restrict__ W2) {
    int bid = blockIdx.x, tid = threadIdx.x;
    int i = bid * 256 + tid;
    unsigned bal = __ballot_sync(0xffffffffu, adj[i] > 0);
    if ((tid & 31) == 0) g_adj[i >> 5] = bal;

    if (bid == 0 && tid <= NH) ((unsigned*)g_mdst)[tid] = 0u;  // ordered -inf
    if (bid < 8192) {
        FEATH[i] = __float2half(features[i]);
    } else if (bid < 8192 + 1024) {
        int k = (bid - 8192) * 256 + tid;
        W1H[k] = __float2half(W1[k]);
    } else if (bid < 8192 + 1024 + 128) {
        int k = (bid - 9216) * 256 + tid;
        W2H[k] = __float2half(W2[k]);
    }
}

// ---------------- HMMA GEMM: C[M,NC] = A[M,K](fp16) @ B[K,NC](fp16) ---------
template<int K, int NC, int LAYER>
__global__ __launch_bounds__(256) void hgemm_kernel() {
    constexpr int BK = 64, NKT = K / BK;
    constexpr int ASTR = BK + 8;
    constexpr int BSTR = NC + 8;
    constexpr int N16 = NC / 32;

    __shared__ __align__(16) __half a_s[128 * ASTR];
    __shared__ __align__(16) __half b_s[BK * BSTR];
    const unsigned a32 = s2u(a_s);
    const unsigned b32 = s2u(b_s);

    const int tid = threadIdx.x;
    const int r0 = blockIdx.x * 128;
    const __half* A  = (LAYER == 1) ? FEATH : X2H;
    const __half* Bm = ((LAYER == 1) ? W1H : W2H) + (size_t)blockIdx.z * K * NC;
    float*  C  = (LAYER == 1) ? (g_h1  + (size_t)blockIdx.z * GN * NC) : g_h2;
    __half* Ch = (LAYER == 1) ? (g_h1h + (size_t)blockIdx.z * GN * NC) : g_h2h;

    const int w = tid >> 5, lane = tid & 31;
    const int wm = (w & 3) * 32;
    const int wn = (w >> 2) * (NC / 2);

    float acc[2][2 * N16][4];
    #pragma unroll
    for (int a = 0; a < 2; a++)
        #pragma unroll
        for (int b = 0; b < 2 * N16; b++)
            #pragma unroll
            for (int c = 0; c < 4; c++) acc[a][b][c] = 0.f;

    for (int kt = 0; kt < NKT; kt++) {
        __syncthreads();
        {
            #pragma unroll
            for (int q = 0; q < 4; q++) {
                int c = tid + q * 256;
                int row = c >> 3, ch = c & 7;
                uint4 v = *(const uint4*)&A[(size_t)(r0 + row) * K + kt * BK + ch * 8];
                *(uint4*)&a_s[row * ASTR + ch * 8] = v;
            }
        }
        {
            #pragma unroll
            for (int q = 0; q < NC / 32; q++) {
                int c = tid + q * 256;
                int row = c / (NC / 8), ch = c % (NC / 8);
                uint4 v = *(const uint4*)&Bm[(size_t)(kt * BK + row) * NC + ch * 8];
                *(uint4*)&b_s[row * BSTR + ch * 8] = v;
            }
        }
        __syncthreads();
        #pragma unroll
        for (int k16 = 0; k16 < BK / 16; k16++) {
            unsigned afr[2][4];
            #pragma unroll
            for (int mi = 0; mi < 2; mi++)
                ldsm4(afr[mi], a32 +
                      ((wm + mi * 16 + (lane & 15)) * ASTR +
                       k16 * 16 + (lane >> 4) * 8) * 2);
            #pragma unroll
            for (int nj = 0; nj < N16; nj++) {
                unsigned bfr[4];
                ldsm4t(bfr, b32 +
                       ((k16 * 16 + (lane & 15)) * BSTR +
                        wn + nj * 16 + (lane >> 4) * 8) * 2);
                #pragma unroll
                for (int mi = 0; mi < 2; mi++) {
                    mma16816(acc[mi][2 * nj],     afr[mi], bfr[0], bfr[1]);
                    mma16816(acc[mi][2 * nj + 1], afr[mi], bfr[2], bfr[3]);
                }
            }
        }
    }

    const int g = lane >> 2, tig = lane & 3;
    #pragma unroll
    for (int mi = 0; mi < 2; mi++) {
        int rr0 = r0 + wm + mi * 16 + g;
        #pragma unroll
        for (int f = 0; f < 2 * N16; f++) {
            int col = wn + f * 8 + tig * 2;
            size_t i0 = (size_t)rr0 * NC + col;
            size_t i1 = (size_t)(rr0 + 8) * NC + col;
            *(float2*)&C[i0] = make_float2(acc[mi][f][0], acc[mi][f][1]);
            *(float2*)&C[i1] = make_float2(acc[mi][f][2], acc[mi][f][3]);
            *(__half2*)&Ch[i0] = __floats2half2_rn(acc[mi][f][0], acc[mi][f][1]);
            *(__half2*)&Ch[i1] = __floats2half2_rn(acc[mi][f][2], acc[mi][f][3]);
        }
    }
}

// ---------------- src/dst projections (+ fused atomic max of dst) -----------
template<int F, int LAYER>
__global__ void srcdst_kernel(const float* __restrict__ a_src,
                              const float* __restrict__ a_dst) {
    const float* Hm = (LAYER == 1) ? g_h1 : g_h2;
    float* so  = (LAYER == 1) ? g_src1 : g_src2;
    float* dso = (LAYER == 1) ? g_dst1 : g_dst2;
    int gw   = (blockIdx.x * blockDim.x + threadIdx.x) >> 5;
    int lane = threadIdx.x & 31;
    int hh = gw / GN;
    const float* row = Hm + (size_t)gw * F;
    float s = 0.f, d = 0.f;
    for (int c = lane; c < F; c += 32) {
        float v = row[c];
        s += v * a_src[hh * F + c];
        d += v * a_dst[hh * F + c];
    }
    for (int o = 16; o; o >>= 1) {
        s += __shfl_xor_sync(0xffffffffu, s, o);
        d += __shfl_xor_sync(0xffffffffu, d, o);
    }
    if (lane == 0) {
        so[gw] = s; dso[gw] = d;
        atomicMax(((unsigned*)g_mdst) + ((LAYER == 1) ? hh : NH), f2ord(d));
    }
}

// ---------------- fused masked-softmax attention (HMMA, register-P) ---------
// A fragments computed directly in m16n8k16 register layout via the
// factorization p = adj * (e>0 ? es_i*ed_j : es2_i*ed2_j). No P smem tile,
// no A ldsm, no per-pair MUFU. Per-tile staging: H (fp16), {ed,ed2} pairs,
// adjacency words. Denominators: warps 0-3 accumulate, quad shfl-reduce.
template<int BM, int NB, int LAYER, int JSPLIT>
__global__ __launch_bounds__(256, 2) void attn_mma_kernel(float* __restrict__ dout) {
    constexpr int KT  = 128;
    constexpr int NTS = (GN / KT) / JSPLIT;
    constexpr int WM  = BM / 4;            // 16
    constexpr int WN  = NB / 2;            // 64 or 32
    constexpr int N16 = WN / 16;           // 4 or 2
    constexpr int HSTR = NB + 8;

    extern __shared__ __align__(16) char smem_c[];
    float*    dpart_s = (float*)smem_c;                  // [BM]
    float*    inv_s   = (float*)(smem_c + 1024);         // [BM]
    float2*   ed2_s   = (float2*)(smem_c + 1280);        // [KT] {ed, ed2}
    unsigned* adj_s   = (unsigned*)(smem_c + 2304);      // [BM*4]
    char*     h_s     = smem_c + 3328;
    const unsigned hb32 = s2u(smem_c) + 3328;

    const int tid = threadIdx.x;
    const int h   = blockIdx.y;
    const int i0  = blockIdx.x * BM;
    const int js  = (JSPLIT > 1) ? blockIdx.z : 0;

    const float* srcv = (LAYER == 1) ? (g_src1 + (size_t)h * GN) : g_src2;
    const float* dstv = (LAYER == 1) ? (g_dst1 + (size_t)h * GN) : g_dst2;
    const __half* Hh  = (LAYER == 1) ? (g_h1h + (size_t)h * GN * FH) : g_h2h;
    const float md = ord2f(((unsigned*)g_mdst)[(LAYER == 1) ? h : NH]);

    const int w = tid >> 5, lane = tid & 31;
    const int g = lane >> 2, tig = lane & 3;
    const int wm = (w & 3) * WM;
    const int wn = (w >> 2) * WN;

    // per-row constants (rows wm+g and wm+g+8)
    const float s0 = srcv[i0 + wm + g];
    const float s1 = srcv[i0 + wm + g + 8];
    float m0 = s0 + md; m0 = (m0 > 0.f) ? m0 : (ALPHA * m0);
    float m1 = s1 + md; m1 = (m1 > 0.f) ? m1 : (ALPHA * m1);
    const float es0 = __expf(s0 - m0), es20 = __expf(0.2f * s0 - m0), tt0 = __expf(-s0);
    const float es1 = __expf(s1 - m1), es21 = __expf(0.2f * s1 - m1), tt1 = __expf(-s1);

    float acc[2 * N16][4];
    #pragma unroll
    for (int b = 0; b < 2 * N16; b++)
        #pragma unroll
        for (int c = 0; c < 4; c++) acc[b][c] = 0.f;
    float dsum0 = 0.f, dsum1 = 0.f;

    for (int jt = js * NTS; jt < (js + 1) * NTS; jt++) {
        const int j0 = jt * KT;
        __syncthreads();                       // prior MMA done with smem
        {   // stage H tile
            #pragma unroll
            for (int q = 0; q < KT * NB / 8 / 256; q++) {
                int c = tid + q * 256;
                int row = c / (NB / 8), ch = c % (NB / 8);
                uint4 v = *(const uint4*)(Hh + (size_t)(j0 + row) * NB + ch * 8);
                *(uint4*)(h_s + row * (HSTR * 2) + ch * 16) = v;
            }
        }
        if (tid < KT) {                        // stage {ed, ed2}
            float d = __ldg(dstv + j0 + tid);
            ed2_s[tid] = make_float2(__expf(d), __expf(0.2f * d));
        }
        {                                      // stage adjacency words
            int rr = tid >> 2, ww = tid & 3;
            adj_s[tid] = __ldg(g_adj + (size_t)(i0 + rr) * (GN / 32) + jt * 4 + ww);
        }
        __syncthreads();

        #pragma unroll
        for (int k16 = 0; k16 < KT / 16; k16++) {
            const int kw = k16 >> 1;
            const int sh = (k16 & 1) * 16;
            unsigned aw0 = adj_s[(wm + g) * 4 + kw];
            unsigned aw1 = adj_s[(wm + g + 8) * 4 + kw];
            float4 lo = *(const float4*)&ed2_s[k16 * 16 + tig * 2];
            float4 hi = *(const float4*)&ed2_s[k16 * 16 + 8 + tig * 2];
            const int b0 = sh + tig * 2, b2 = sh + 8 + tig * 2;
            float p00 = ((aw0 >> b0) & 1u)       ? ((lo.x > tt0) ? es0 * lo.x : es20 * lo.y) : 0.f;
            float p01 = ((aw0 >> (b0 + 1)) & 1u) ? ((lo.z > tt0) ? es0 * lo.z : es20 * lo.w) : 0.f;
            float p02 = ((aw0 >> b2) & 1u)       ? ((hi.x > tt0) ? es0 * hi.x : es20 * hi.y) : 0.f;
            float p03 = ((aw0 >> (b2 + 1)) & 1u) ? ((hi.z > tt0) ? es0 * hi.z : es20 * hi.w) : 0.f;
            float p10 = ((aw1 >> b0) & 1u)       ? ((lo.x > tt1) ? es1 * lo.x : es21 * lo.y) : 0.f;
            float p11 = ((aw1 >> (b0 + 1)) & 1u) ? ((lo.z > tt1) ? es1 * lo.z : es21 * lo.w) : 0.f;
            float p12 = ((aw1 >> b2) & 1u)       ? ((hi.x > tt1) ? es1 * hi.x : es21 * hi.y) : 0.f;
            float p13 = ((aw1 >> (b2 + 1)) & 1u) ? ((hi.z > tt1) ? es1 * hi.z : es21 * hi.w) : 0.f;
            if (w < 4) {
                dsum0 += (p00 + p01) + (p02 + p03);
                dsum1 += (p10 + p11) + (p12 + p13);
            }
            unsigned afr[4];
            afr[0] = h2u(p00, p01);
            afr[1] = h2u(p10, p11);
            afr[2] = h2u(p02, p03);
            afr[3] = h2u(p12, p13);
            #pragma unroll
            for (int nj = 0; nj < N16; nj++) {
                unsigned bfr[4];
                ldsm4t(bfr, hb32 +
                       ((k16 * 16 + (lane & 15)) * HSTR +
                        wn + nj * 16 + (lane >> 4) * 8) * 2);
                mma16816(acc[2 * nj],     afr, bfr[0], bfr[1]);
                mma16816(acc[2 * nj + 1], afr, bfr[2], bfr[3]);
            }
        }
    }

    // exact fp32 denominators (warps 0-3 cover all rows once)
    if (w < 4) {
        dsum0 += __shfl_xor_sync(0xffffffffu, dsum0, 1);
        dsum0 += __shfl_xor_sync(0xffffffffu, dsum0, 2);
        dsum1 += __shfl_xor_sync(0xffffffffu, dsum1, 1);
        dsum1 += __shfl_xor_sync(0xffffffffu, dsum1, 2);
        if (tig == 0) {
            dpart_s[wm + g]     = dsum0;
            dpart_s[wm + g + 8] = dsum1;
        }
    }
    __syncthreads();
    if (tid < BM) {
        if (LAYER == 1) inv_s[tid] = 1.f / dpart_s[tid];
        else            PDEN[js * GN + i0 + tid] = dpart_s[tid];
    }
    __syncthreads();

    if (LAYER == 1) {
        int rr0 = wm + g;
        float inv0 = inv_s[rr0], inv1 = inv_s[rr0 + 8];
        #pragma unroll
        for (int f = 0; f < 2 * N16; f++) {
            int col = wn + f * 8 + tig * 2;
            float v0 = acc[f][0] * inv0;
            float v1 = acc[f][1] * inv0;
            float v2 = acc[f][2] * inv1;
            float v3 = acc[f][3] * inv1;
            v0 = (v0 > 0.f) ? v0 : expm1f(v0);
            v1 = (v1 > 0.f) ? v1 : expm1f(v1);
            v2 = (v2 > 0.f) ? v2 : expm1f(v2);
            v3 = (v3 > 0.f) ? v3 : expm1f(v3);
            size_t o0 = (size_t)(i0 + rr0) * (NH * FH) + h * FH + col;
            size_t o1 = (size_t)(i0 + rr0 + 8) * (NH * FH) + h * FH + col;
            *(__half2*)&X2H[o0] = __floats2half2_rn(v0, v1);
            *(__half2*)&X2H[o1] = __floats2half2_rn(v2, v3);
        }
    } else {
        int rr0 = wm + g;
        #pragma unroll
        for (int f = 0; f < 2 * N16; f++) {
            int col = wn + f * 8 + tig * 2;
            float* o0 = PNUM + (size_t)js * GN * FOUT + (size_t)(i0 + rr0) * FOUT + col;
            float* o1 = PNUM + (size_t)js * GN * FOUT + (size_t)(i0 + rr0 + 8) * FOUT + col;
            *(float2*)o0 = make_float2(acc[f][0], acc[f][1]);
            *(float2*)o1 = make_float2(acc[f][2], acc[f][3]);
        }
    }
}

// ---------------- combine: sum partials, normalize, ELU, log_softmax --------
__global__ void combine_kernel(float* __restrict__ out) {
    int gw   = (blockIdx.x * blockDim.x + threadIdx.x) >> 5;   // row
    int lane = threadIdx.x & 31;
    float den = 0.f;
    #pragma unroll
    for (int js = 0; js < 4; js++) den += PDEN[js * GN + gw];
    float inv = 1.f / den;
    float v0 = 0.f, v1 = 0.f;
    #pragma unroll
    for (int js = 0; js < 4; js++) {
        const float* p = PNUM + (size_t)js * GN * FOUT + (size_t)gw * FOUT;
        v0 += p[lane];
        v1 += p[lane + 32];
    }
    v0 *= inv; v1 *= inv;
    v0 = (v0 > 0.f) ? v0 : expm1f(v0);
    v1 = (v1 > 0.f) ? v1 : expm1f(v1);
    float m = fmaxf(v0, v1);
    #pragma unroll
    for (int o = 16; o; o >>= 1) m = fmaxf(m, __shfl_xor_sync(0xffffffffu, m, o));
    float s = __expf(v0 - m) + __expf(v1 - m);
    #pragma unroll
    for (int o = 16; o; o >>= 1) s += __shfl_xor_sync(0xffffffffu, s, o);
    float lse = m + logf(s);
    out[(size_t)gw * FOUT + lane]      = v0 - lse;
    out[(size_t)gw * FOUT + lane + 32] = v1 - lse;
}

// ---------------- launch ----------------------------------------------------
extern "C" void kernel_launch(void* const* d_in, const int* in_sizes, int n_in,
                              void* d_out, int out_size) {
    const float* features = (const float*)d_in[0];
    const int*   adj      = (const int*)d_in[1];
    const float* W1  = (const float*)d_in[2];
    const float* a1s = (const float*)d_in[3];
    const float* a1d = (const float*)d_in[4];
    const float* W2  = (const float*)d_in[5];
    const float* a2s = (const float*)d_in[6];
    const float* a2d = (const float*)d_in[7];
    float* out = (float*)d_out;

    const int SMEM1 = 3328 + 128 * 136 * 2;   // 38144
    const int SMEM2 = 3328 + 128 * 72 * 2;    // 21760
    cudaFuncSetAttribute(attn_mma_kernel<64, FH, 1, 1>,
                         cudaFuncAttributeMaxDynamicSharedMemorySize, SMEM1);
    cudaFuncSetAttribute(attn_mma_kernel<64, FOUT, 2, 4>,
                         cudaFuncAttributeMaxDynamicSharedMemorySize, SMEM2);

    pack_adj_kernel<<<(GN * GN) / 256, 256>>>(adj, features, W1, W2);

    // layer 1
    hgemm_kernel<FIN, FH, 1><<<dim3(GN / 128, 1, NH), 256>>>();
    srcdst_kernel<FH, 1><<<(NH * GN) / 8, 256>>>(a1s, a1d);
    attn_mma_kernel<64, FH, 1, 1><<<dim3(GN / 64, NH, 1), 256, SMEM1>>>(nullptr);

    // layer 2
    hgemm_kernel<NH * FH, FOUT, 2><<<dim3(GN / 128, 1, 1), 256>>>();
    srcdst_kernel<FOUT, 2><<<GN / 8, 256>>>(a2s, a2d);
    attn_mma_kernel<64, FOUT, 2, 4><<<dim3(GN / 64, 1, 4), 256, SMEM2>>>(nullptr);
    combine_kernel<<<GN / 8, 256>>>(out);
}

// round 14
// speedup vs baseline: 4.1596x; 1.0090x over previous
#include <cuda_runtime.h>
#include <cuda_fp16.h>
#include <cstdint>
#include <math.h>

#define GN   4096
#define FIN  512
#define FH   128
#define NH   4
#define FOUT 64
#define ALPHA 0.2f

// ---------------- scratch: EXACT same global set/sizes as the passing round --
__device__ __align__(16) float  g_h1[NH * GN * FH];   // fp32 H1; later aliased as fp16 x2h
__device__ float  g_h2[GN * FOUT];
__device__ __half g_h1h[NH * GN * FH];                // fp16 H1 (attn B operand)
__device__ __half g_h2h[GN * FOUT];
__device__ float  g_src1[NH * GN];
__device__ float  g_dst1[NH * GN];
__device__ float  g_src2[GN];
__device__ float  g_dst2[GN];
__device__ float  g_mdst[NH + 1];                     // ordered-uint encoded via casts
__device__ unsigned g_adj[GN * GN / 32];              // bit mask, 2 MB
__device__ __align__(16) float  g_x2[GN * (NH * FH)]; // aliased: feath|W1h|W2h, then attn2 partials

// half-aliased views (offsets in halfs; all 16B aligned)
#define FEATH ((__half*)g_x2)                          // 2,097,152 halfs
#define W1H   (((__half*)g_x2) + 2097152)              // 262,144 halfs
#define W2H   (((__half*)g_x2) + 2359296)              // 32,768 halfs
#define X2H   ((__half*)g_h1)                          // 2,097,152 halfs
// attn2 partial buffers (g_x2 is dead by attn2 time)
#define PNUM  ((float*)g_x2)                           // [4][GN][FOUT] = 4 MB
#define PDEN  (((float*)g_x2) + 1048576)               // [4][GN]

// ---------------- PTX helpers ------------------------------------------------
__device__ __forceinline__ unsigned s2u(const void* p) {
    unsigned a;
    asm("{ .reg .u64 t; cvta.to.shared.u64 t, %1; cvt.u32.u64 %0, t; }"
        : "=r"(a) : "l"(p));
    return a;
}

__device__ __forceinline__ void ldsm4(unsigned* d, unsigned addr) {
    asm volatile("ldmatrix.sync.aligned.m8n8.x4.shared.b16 {%0,%1,%2,%3}, [%4];"
                 : "=r"(d[0]), "=r"(d[1]), "=r"(d[2]), "=r"(d[3]) : "r"(addr));
}

__device__ __forceinline__ void ldsm4t(unsigned* d, unsigned addr) {
    asm volatile("ldmatrix.sync.aligned.m8n8.x4.trans.shared.b16 {%0,%1,%2,%3}, [%4];"
                 : "=r"(d[0]), "=r"(d[1]), "=r"(d[2]), "=r"(d[3]) : "r"(addr));
}

__device__ __forceinline__ void mma16816(float* c, const unsigned* a,
                                         unsigned b0, unsigned b1) {
    asm volatile(
        "mma.sync.aligned.m16n8k16.row.col.f32.f16.f16.f32 "
        "{%0,%1,%2,%3}, {%4,%5,%6,%7}, {%8,%9}, {%0,%1,%2,%3};"
        : "+f"(c[0]), "+f"(c[1]), "+f"(c[2]), "+f"(c[3])
        : "r"(a[0]), "r"(a[1]), "r"(a[2]), "r"(a[3]), "r"(b0), "r"(b1));
}

// monotone float<->uint map for atomicMax on signed floats
__device__ __forceinline__ unsigned f2ord(float f) {
    unsigned u = __float_as_uint(f);
    return (u & 0x80000000u) ? ~u : (u | 0x80000000u);
}
__device__ __forceinline__ float ord2f(unsigned u) {
    return (u & 0x80000000u) ? __uint_as_float(u & 0x7fffffffu)
                             : __uint_as_float(~u);
}

// ---------------- pack: adjacency bits + fp16 conversions + mdst init -------
__global__ void pack_adj_kernel(const int* __restrict__ adj,
                                const float* __restrict__ features,
                                const float* __restrict__ W1,
                                const float* __restrict__ W2) {
    int bid = blockIdx.x, tid = threadIdx.x;
    int i = bid * 256 + tid;
    unsigned bal = __ballot_sync(0xffffffffu, adj[i] > 0);
    if ((tid & 31) == 0) g_adj[i >> 5] = bal;

    if (bid == 0 && tid <= NH) ((unsigned*)g_mdst)[tid] = 0u;  // ordered -inf
    if (bid < 8192) {
        FEATH[i] = __float2half(features[i]);
    } else if (bid < 8192 + 1024) {
        int k = (bid - 8192) * 256 + tid;
        W1H[k] = __float2half(W1[k]);
    } else if (bid < 8192 + 1024 + 128) {
        int k = (bid - 9216) * 256 + tid;
        W2H[k] = __float2half(W2[k]);
    }
}

// ---------------- HMMA GEMM: C[M,NC] = A[M,K](fp16) @ B[K,NC](fp16) ---------
template<int K, int NC, int LAYER>
__global__ __launch_bounds__(256) void hgemm_kernel() {
    constexpr int BK = 64, NKT = K / BK;
    constexpr int ASTR = BK + 8;
    constexpr int BSTR = NC + 8;
    constexpr int N16 = NC / 32;

    __shared__ __align__(16) __half a_s[128 * ASTR];
    __shared__ __align__(16) __half b_s[BK * BSTR];
    const unsigned a32 = s2u(a_s);
    const unsigned b32 = s2u(b_s);

    const int tid = threadIdx.x;
    const int r0 = blockIdx.x * 128;
    const __half* A  = (LAYER == 1) ? FEATH : X2H;
    const __half* Bm = ((LAYER == 1) ? W1H : W2H) + (size_t)blockIdx.z * K * NC;
    float*  C  = (LAYER == 1) ? (g_h1  + (size_t)blockIdx.z * GN * NC) : g_h2;
    __half* Ch = (LAYER == 1) ? (g_h1h + (size_t)blockIdx.z * GN * NC) : g_h2h;

    const int w = tid >> 5, lane = tid & 31;
    const int wm = (w & 3) * 32;
    const int wn = (w >> 2) * (NC / 2);

    float acc[2][2 * N16][4];
    #pragma unroll
    for (int a = 0; a < 2; a++)
        #pragma unroll
        for (int b = 0; b < 2 * N16; b++)
            #pragma unroll
            for (int c = 0; c < 4; c++) acc[a][b][c] = 0.f;

    for (int kt = 0; kt < NKT; kt++) {
        __syncthreads();
        {
            #pragma unroll
            for (int q = 0; q < 4; q++) {
                int c = tid + q * 256;
                int row = c >> 3, ch = c & 7;
                uint4 v = *(const uint4*)&A[(size_t)(r0 + row) * K + kt * BK + ch * 8];
                *(uint4*)&a_s[row * ASTR + ch * 8] = v;
            }
        }
        {
            #pragma unroll
            for (int q = 0; q < NC / 32; q++) {
                int c = tid + q * 256;
                int row = c / (NC / 8), ch = c % (NC / 8);
                uint4 v = *(const uint4*)&Bm[(size_t)(kt * BK + row) * NC + ch * 8];
                *(uint4*)&b_s[row * BSTR + ch * 8] = v;
            }
        }
        __syncthreads();
        #pragma unroll
        for (int k16 = 0; k16 < BK / 16; k16++) {
            unsigned afr[2][4];
            #pragma unroll
            for (int mi = 0; mi < 2; mi++)
                ldsm4(afr[mi], a32 +
                      ((wm + mi * 16 + (lane & 15)) * ASTR +
                       k16 * 16 + (lane >> 4) * 8) * 2);
            #pragma unroll
            for (int nj = 0; nj < N16; nj++) {
                unsigned bfr[4];
                ldsm4t(bfr, b32 +
                       ((k16 * 16 + (lane & 15)) * BSTR +
                        wn + nj * 16 + (lane >> 4) * 8) * 2);
                #pragma unroll
                for (int mi = 0; mi < 2; mi++) {
                    mma16816(acc[mi][2 * nj],     afr[mi], bfr[0], bfr[1]);
                    mma16816(acc[mi][2 * nj + 1], afr[mi], bfr[2], bfr[3]);
                }
            }
        }
    }

    const int g = lane >> 2, tig = lane & 3;
    #pragma unroll
    for (int mi = 0; mi < 2; mi++) {
        int rr0 = r0 + wm + mi * 16 + g;
        #pragma unroll
        for (int f = 0; f < 2 * N16; f++) {
            int col = wn + f * 8 + tig * 2;
            size_t i0 = (size_t)rr0 * NC + col;
            size_t i1 = (size_t)(rr0 + 8) * NC + col;
            *(float2*)&C[i0] = make_float2(acc[mi][f][0], acc[mi][f][1]);
            *(float2*)&C[i1] = make_float2(acc[mi][f][2], acc[mi][f][3]);
            *(__half2*)&Ch[i0] = __floats2half2_rn(acc[mi][f][0], acc[mi][f][1]);
            *(__half2*)&Ch[i1] = __floats2half2_rn(acc[mi][f][2], acc[mi][f][3]);
        }
    }
}

// ---------------- src/dst projections (+ fused atomic max of dst) -----------
template<int F, int LAYER>
__global__ void srcdst_kernel(const float* __restrict__ a_src,
                              const float* __restrict__ a_dst) {
    const float* Hm = (LAYER == 1) ? g_h1 : g_h2;
    float* so  = (LAYER == 1) ? g_src1 : g_src2;
    float* dso = (LAYER == 1) ? g_dst1 : g_dst2;
    int gw   = (blockIdx.x * blockDim.x + threadIdx.x) >> 5;
    int lane = threadIdx.x & 31;
    int hh = gw / GN;
    const float* row = Hm + (size_t)gw * F;
    float s = 0.f, d = 0.f;
    for (int c = lane; c < F; c += 32) {
        float v = row[c];
        s += v * a_src[hh * F + c];
        d += v * a_dst[hh * F + c];
    }
    for (int o = 16; o; o >>= 1) {
        s += __shfl_xor_sync(0xffffffffu, s, o);
        d += __shfl_xor_sync(0xffffffffu, d, o);
    }
    if (lane == 0) {
        so[gw] = s; dso[gw] = d;
        atomicMax(((unsigned*)g_mdst) + ((LAYER == 1) ? hh : NH), f2ord(d));
    }
}

// ---------------- fused masked-softmax attention (HMMA, half2 register-P) ---
// exp(lrelu(e)) = max(exp(e), exp(0.2e)) factorizes to
// p = adj * max(esA_i*edA_j, esB_i*edB_j), all factors rescaled into [0,1]
// (fp16-safe). A fragments built with HMUL2/HMAX2 + LUT mask; denominators
// via a ones-B MMA per k16 (exact fp32 sum of fp16 p, matches numerator).
template<int BM, int NB, int LAYER, int JSPLIT>
__global__ __launch_bounds__(256, 2) void attn_mma_kernel(float* __restrict__ dout) {
    constexpr int KT  = 128;
    constexpr int NTS = (GN / KT) / JSPLIT;
    constexpr int WM  = BM / 4;            // 16
    constexpr int WN  = NB / 2;            // 64 or 32
    constexpr int N16 = WN / 16;           // 4 or 2
    constexpr int HSTR = NB + 8;
    constexpr unsigned ONES2 = 0x3C003C00u;

    extern __shared__ __align__(16) char smem_c[];
    float*    dpart_s = (float*)smem_c;                  // [64]
    float*    inv_s   = (float*)(smem_c + 256);          // [64]
    unsigned* lut_s   = (unsigned*)(smem_c + 512);       // [4]
    uint2*    edp_s   = (uint2*)(smem_c + 640);          // [64] {edA pair, edB pair}
    unsigned* adj_s   = (unsigned*)(smem_c + 1152);      // [256]
    char*     h_s     = smem_c + 2304;
    const unsigned hb32 = s2u(smem_c) + 2304;

    const int tid = threadIdx.x;
    const int h   = blockIdx.y;
    const int i0  = blockIdx.x * BM;
    const int js  = (JSPLIT > 1) ? blockIdx.z : 0;

    const float* srcv = (LAYER == 1) ? (g_src1 + (size_t)h * GN) : g_src2;
    const float* dstv = (LAYER == 1) ? (g_dst1 + (size_t)h * GN) : g_dst2;
    const __half* Hh  = (LAYER == 1) ? (g_h1h + (size_t)h * GN * FH) : g_h2h;
    const float md = ord2f(((unsigned*)g_mdst)[(LAYER == 1) ? h : NH]);

    if (tid < 4)
        lut_s[tid] = ((tid & 1) ? 0x0000FFFFu : 0u) | ((tid & 2) ? 0xFFFF0000u : 0u);

    const int w = tid >> 5, lane = tid & 31;
    const int g = lane >> 2, tig = lane & 3;
    const int wm = (w & 3) * WM;
    const int wn = (w >> 2) * WN;

    // per-row factors (rows wm+g and wm+g+8), all <= 1
    const float s0 = srcv[i0 + wm + g];
    const float s1 = srcv[i0 + wm + g + 8];
    float t0 = s0 + md; float m0 = (t0 > 0.f) ? t0 : (ALPHA * t0);
    float t1 = s1 + md; float m1 = (t1 > 0.f) ? t1 : (ALPHA * t1);
    const __half2 esA0 = __float2half2_rn(__expf(t0 - m0));
    const __half2 esB0 = __float2half2_rn(__expf(0.2f * t0 - m0));
    const __half2 esA1 = __float2half2_rn(__expf(t1 - m1));
    const __half2 esB1 = __float2half2_rn(__expf(0.2f * t1 - m1));

    float acc[2 * N16][4];
    #pragma unroll
    for (int b = 0; b < 2 * N16; b++)
        #pragma unroll
        for (int c = 0; c < 4; c++) acc[b][c] = 0.f;
    float accd[4] = {0.f, 0.f, 0.f, 0.f};

    for (int jt = js * NTS; jt < (js + 1) * NTS; jt++) {
        const int j0 = jt * KT;
        __syncthreads();                       // prior MMA done with smem
        {   // stage H tile
            #pragma unroll
            for (int q = 0; q < KT * NB / 8 / 256; q++) {
                int c = tid + q * 256;
                int row = c / (NB / 8), ch = c % (NB / 8);
                uint4 v = *(const uint4*)(Hh + (size_t)(j0 + row) * NB + ch * 8);
                *(uint4*)(h_s + row * (HSTR * 2) + ch * 16) = v;
            }
        }
        if (tid < KT / 2) {                    // stage {edA, edB} half2 pairs
            float d0 = __ldg(dstv + j0 + 2 * tid)     - md;
            float d1 = __ldg(dstv + j0 + 2 * tid + 1) - md;
            __half2 ea = __floats2half2_rn(__expf(d0), __expf(d1));
            __half2 eb = __floats2half2_rn(__expf(0.2f * d0), __expf(0.2f * d1));
            uint2 e;
            e.x = *(unsigned*)&ea;
            e.y = *(unsigned*)&eb;
            edp_s[tid] = e;
        }
        {                                      // stage adjacency words
            int rr = tid >> 2, ww = tid & 3;
            adj_s[tid] = __ldg(g_adj + (size_t)(i0 + rr) * (GN / 32) + jt * 4 + ww);
        }
        __syncthreads();

        #pragma unroll
        for (int k16 = 0; k16 < KT / 16; k16++) {
            const int kw = k16 >> 1;
            const int sh = (k16 & 1) * 16;
            unsigned aw0 = adj_s[(wm + g) * 4 + kw];
            unsigned aw1 = adj_s[(wm + g + 8) * 4 + kw];
            uint2 elo = edp_s[k16 * 8 + tig];
            uint2 ehi = edp_s[k16 * 8 + 4 + tig];
            __half2 eAlo = *(__half2*)&elo.x, eBlo = *(__half2*)&elo.y;
            __half2 eAhi = *(__half2*)&ehi.x, eBhi = *(__half2*)&ehi.y;
            const int b0 = sh + tig * 2, b2 = sh + 8 + tig * 2;
            __half2 p0lo = __hmax2(__hmul2(esA0, eAlo), __hmul2(esB0, eBlo));
            __half2 p1lo = __hmax2(__hmul2(esA1, eAlo), __hmul2(esB1, eBlo));
            __half2 p0hi = __hmax2(__hmul2(esA0, eAhi), __hmul2(esB0, eBhi));
            __half2 p1hi = __hmax2(__hmul2(esA1, eAhi), __hmul2(esB1, eBhi));
            unsigned afr[4];
            afr[0] = (*(unsigned*)&p0lo) & lut_s[(aw0 >> b0) & 3u];
            afr[1] = (*(unsigned*)&p1lo) & lut_s[(aw1 >> b0) & 3u];
            afr[2] = (*(unsigned*)&p0hi) & lut_s[(aw0 >> b2) & 3u];
            afr[3] = (*(unsigned*)&p1hi) & lut_s[(aw1 >> b2) & 3u];
            if (w < 4) mma16816(accd, afr, ONES2, ONES2);   // row sums (denom)
            #pragma unroll
            for (int nj = 0; nj < N16; nj++) {
                unsigned bfr[4];
                ldsm4t(bfr, hb32 +
                       ((k16 * 16 + (lane & 15)) * HSTR +
                        wn + nj * 16 + (lane >> 4) * 8) * 2);
                mma16816(acc[2 * nj],     afr, bfr[0], bfr[1]);
                mma16816(acc[2 * nj + 1], afr, bfr[2], bfr[3]);
            }
        }
    }

    // denominators: accd[0]=row wm+g, accd[2]=row wm+g+8 (all tig identical)
    if (w < 4 && tig == 0) {
        dpart_s[wm + g]     = accd[0];
        dpart_s[wm + g + 8] = accd[2];
    }
    __syncthreads();
    if (tid < BM) {
        if (LAYER == 1) inv_s[tid] = 1.f / dpart_s[tid];
        else            PDEN[js * GN + i0 + tid] = dpart_s[tid];
    }
    __syncthreads();

    if (LAYER == 1) {
        int rr0 = wm + g;
        float inv0 = inv_s[rr0], inv1 = inv_s[rr0 + 8];
        #pragma unroll
        for (int f = 0; f < 2 * N16; f++) {
            int col = wn + f * 8 + tig * 2;
            float v0 = acc[f][0] * inv0;
            float v1 = acc[f][1] * inv0;
            float v2 = acc[f][2] * inv1;
            float v3 = acc[f][3] * inv1;
            v0 = (v0 > 0.f) ? v0 : expm1f(v0);
            v1 = (v1 > 0.f) ? v1 : expm1f(v1);
            v2 = (v2 > 0.f) ? v2 : expm1f(v2);
            v3 = (v3 > 0.f) ? v3 : expm1f(v3);
            size_t o0 = (size_t)(i0 + rr0) * (NH * FH) + h * FH + col;
            size_t o1 = (size_t)(i0 + rr0 + 8) * (NH * FH) + h * FH + col;
            *(__half2*)&X2H[o0] = __floats2half2_rn(v0, v1);
            *(__half2*)&X2H[o1] = __floats2half2_rn(v2, v3);
        }
    } else {
        int rr0 = wm + g;
        #pragma unroll
        for (int f = 0; f < 2 * N16; f++) {
            int col = wn + f * 8 + tig * 2;
            float* o0 = PNUM + (size_t)js * GN * FOUT + (size_t)(i0 + rr0) * FOUT + col;
            float* o1 = PNUM + (size_t)js * GN * FOUT + (size_t)(i0 + rr0 + 8) * FOUT + col;
            *(float2*)o0 = make_float2(acc[f][0], acc[f][1]);
            *(float2*)o1 = make_float2(acc[f][2], acc[f][3]);
        }
    }
}

// ---------------- combine: sum partials, normalize, ELU, log_softmax --------
__global__ void combine_kernel(float* __restrict__ out) {
    int gw   = (blockIdx.x * blockDim.x + threadIdx.x) >> 5;   // row
    int lane = threadIdx.x & 31;
    float den = 0.f;
    #pragma unroll
    for (int js = 0; js < 4; js++) den += PDEN[js * GN + gw];
    float inv = 1.f / den;
    float v0 = 0.f, v1 = 0.f;
    #pragma unroll
    for (int js = 0; js < 4; js++) {
        const float* p = PNUM + (size_t)js * GN * FOUT + (size_t)gw * FOUT;
        v0 += p[lane];
        v1 += p[lane + 32];
    }
    v0 *= inv; v1 *= inv;
    v0 = (v0 > 0.f) ? v0 : expm1f(v0);
    v1 = (v1 > 0.f) ? v1 : expm1f(v1);
    float m = fmaxf(v0, v1);
    #pragma unroll
    for (int o = 16; o; o >>= 1) m = fmaxf(m, __shfl_xor_sync(0xffffffffu, m, o));
    float s = __expf(v0 - m) + __expf(v1 - m);
    #pragma unroll
    for (int o = 16; o; o >>= 1) s += __shfl_xor_sync(0xffffffffu, s, o);
    float lse = m + logf(s);
    out[(size_t)gw * FOUT + lane]      = v0 - lse;
    out[(size_t)gw * FOUT + lane + 32] = v1 - lse;
}

// ---------------- launch ----------------------------------------------------
extern "C" void kernel_launch(void* const* d_in, const int* in_sizes, int n_in,
                              void* d_out, int out_size) {
    const float* features = (const float*)d_in[0];
    const int*   adj      = (const int*)d_in[1];
    const float* W1  = (const float*)d_in[2];
    const float* a1s = (const float*)d_in[3];
    const float* a1d = (const float*)d_in[4];
    const float* W2  = (const float*)d_in[5];
    const float* a2s = (const float*)d_in[6];
    const float* a2d = (const float*)d_in[7];
    float* out = (float*)d_out;

    const int SMEM1 = 2304 + 128 * 136 * 2;   // 37120
    const int SMEM2 = 2304 + 128 * 72 * 2;    // 20736
    cudaFuncSetAttribute(attn_mma_kernel<64, FH, 1, 1>,
                         cudaFuncAttributeMaxDynamicSharedMemorySize, SMEM1);
    cudaFuncSetAttribute(attn_mma_kernel<64, FOUT, 2, 4>,
                         cudaFuncAttributeMaxDynamicSharedMemorySize, SMEM2);

    pack_adj_kernel<<<(GN * GN) / 256, 256>>>(adj, features, W1, W2);

    // layer 1
    hgemm_kernel<FIN, FH, 1><<<dim3(GN / 128, 1, NH), 256>>>();
    srcdst_kernel<FH, 1><<<(NH * GN) / 8, 256>>>(a1s, a1d);
    attn_mma_kernel<64, FH, 1, 1><<<dim3(GN / 64, NH, 1), 256, SMEM1>>>(nullptr);

    // layer 2
    hgemm_kernel<NH * FH, FOUT, 2><<<dim3(GN / 128, 1, 1), 256>>>();
    srcdst_kernel<FOUT, 2><<<GN / 8, 256>>>(a2s, a2d);
    attn_mma_kernel<64, FOUT, 2, 4><<<dim3(GN / 64, 1, 4), 256, SMEM2>>>(nullptr);
    combine_kernel<<<GN / 8, 256>>>(out);
}

// round 15
// speedup vs baseline: 4.2790x; 1.0287x over previous
#include <cuda_runtime.h>
#include <cuda_fp16.h>
#include <cstdint>
#include <math.h>

#define GN   4096
#define FIN  512
#define FH   128
#define NH   4
#define FOUT 64
#define ALPHA 0.2f

// ---------------- scratch: EXACT same global set/sizes as the passing round --
__device__ __align__(16) float  g_h1[NH * GN * FH];   // fp32 H1; later aliased as fp16 x2h
__device__ float  g_h2[GN * FOUT];
__device__ __half g_h1h[NH * GN * FH];                // fp16 H1 (attn B operand)
__device__ __half g_h2h[GN * FOUT];
__device__ float  g_src1[NH * GN];
__device__ float  g_dst1[NH * GN];
__device__ float  g_src2[GN];
__device__ float  g_dst2[GN];
__device__ float  g_mdst[NH + 1];                     // ordered-uint encoded via casts
__device__ unsigned g_adj[GN * GN / 32];              // bit mask, 2 MB
__device__ __align__(16) float  g_x2[GN * (NH * FH)]; // aliased: feath|W1h|W2h, then attn2 partials

// half-aliased views (offsets in halfs; all 16B aligned)
#define FEATH ((__half*)g_x2)                          // 2,097,152 halfs
#define W1H   (((__half*)g_x2) + 2097152)              // 262,144 halfs
#define W2H   (((__half*)g_x2) + 2359296)              // 32,768 halfs
#define X2H   ((__half*)g_h1)                          // 2,097,152 halfs
// attn2 partial buffers (g_x2 is dead by attn2 time)
#define PNUM  ((float*)g_x2)                           // [4][GN][FOUT] = 4 MB
#define PDEN  (((float*)g_x2) + 1048576)               // [4][GN]

// ---------------- PTX helpers ------------------------------------------------
__device__ __forceinline__ unsigned s2u(const void* p) {
    unsigned a;
    asm("{ .reg .u64 t; cvta.to.shared.u64 t, %1; cvt.u32.u64 %0, t; }"
        : "=r"(a) : "l"(p));
    return a;
}

__device__ __forceinline__ void ldsm4(unsigned* d, unsigned addr) {
    asm volatile("ldmatrix.sync.aligned.m8n8.x4.shared.b16 {%0,%1,%2,%3}, [%4];"
                 : "=r"(d[0]), "=r"(d[1]), "=r"(d[2]), "=r"(d[3]) : "r"(addr));
}

__device__ __forceinline__ void ldsm4t(unsigned* d, unsigned addr) {
    asm volatile("ldmatrix.sync.aligned.m8n8.x4.trans.shared.b16 {%0,%1,%2,%3}, [%4];"
                 : "=r"(d[0]), "=r"(d[1]), "=r"(d[2]), "=r"(d[3]) : "r"(addr));
}

__device__ __forceinline__ void mma16816(float* c, const unsigned* a,
                                         unsigned b0, unsigned b1) {
    asm volatile(
        "mma.sync.aligned.m16n8k16.row.col.f32.f16.f16.f32 "
        "{%0,%1,%2,%3}, {%4,%5,%6,%7}, {%8,%9}, {%0,%1,%2,%3};"
        : "+f"(c[0]), "+f"(c[1]), "+f"(c[2]), "+f"(c[3])
        : "r"(a[0]), "r"(a[1]), "r"(a[2]), "r"(a[3]), "r"(b0), "r"(b1));
}

#define CP_ASYNC16(s, g) \
    asm volatile("cp.async.cg.shared.global [%0], [%1], 16;" :: "r"(s), "l"(g))
#define CP_COMMIT() asm volatile("cp.async.commit_group;")
#define CP_WAIT(n)  asm volatile("cp.async.wait_group %0;" :: "n"(n))

// monotone float<->uint map for atomicMax on signed floats
__device__ __forceinline__ unsigned f2ord(float f) {
    unsigned u = __float_as_uint(f);
    return (u & 0x80000000u) ? ~u : (u | 0x80000000u);
}
__device__ __forceinline__ float ord2f(unsigned u) {
    return (u & 0x80000000u) ? __uint_as_float(u & 0x7fffffffu)
                             : __uint_as_float(~u);
}

// ---------------- pack: adjacency bits + fp16 conversions + mdst init -------
__global__ void pack_adj_kernel(const int* __restrict__ adj,
                                const float* __restrict__ features,
                                const float* __restrict__ W1,
                                const float* __restrict__ W2) {
    int bid = blockIdx.x, tid = threadIdx.x;
    int i = bid * 256 + tid;
    unsigned bal = __ballot_sync(0xffffffffu, adj[i] > 0);
    if ((tid & 31) == 0) g_adj[i >> 5] = bal;

    if (bid == 0 && tid <= NH) ((unsigned*)g_mdst)[tid] = 0u;  // ordered -inf
    if (bid < 8192) {
        FEATH[i] = __float2half(features[i]);
    } else if (bid < 8192 + 1024) {
        int k = (bid - 8192) * 256 + tid;
        W1H[k] = __float2half(W1[k]);
    } else if (bid < 8192 + 1024 + 128) {
        int k = (bid - 9216) * 256 + tid;
        W2H[k] = __float2half(W2[k]);
    }
}

// ---------------- HMMA GEMM: C[M,NC] = A[M,K](fp16) @ B[K,NC](fp16) ---------
template<int K, int NC, int LAYER>
__global__ __launch_bounds__(256) void hgemm_kernel() {
    constexpr int BK = 64, NKT = K / BK;
    constexpr int ASTR = BK + 8;
    constexpr int BSTR = NC + 8;
    constexpr int N16 = NC / 32;

    __shared__ __align__(16) __half a_s[128 * ASTR];
    __shared__ __align__(16) __half b_s[BK * BSTR];
    const unsigned a32 = s2u(a_s);
    const unsigned b32 = s2u(b_s);

    const int tid = threadIdx.x;
    const int r0 = blockIdx.x * 128;
    const __half* A  = (LAYER == 1) ? FEATH : X2H;
    const __half* Bm = ((LAYER == 1) ? W1H : W2H) + (size_t)blockIdx.z * K * NC;
    float*  C  = (LAYER == 1) ? (g_h1  + (size_t)blockIdx.z * GN * NC) : g_h2;
    __half* Ch = (LAYER == 1) ? (g_h1h + (size_t)blockIdx.z * GN * NC) : g_h2h;

    const int w = tid >> 5, lane = tid & 31;
    const int wm = (w & 3) * 32;
    const int wn = (w >> 2) * (NC / 2);

    float acc[2][2 * N16][4];
    #pragma unroll
    for (int a = 0; a < 2; a++)
        #pragma unroll
        for (int b = 0; b < 2 * N16; b++)
            #pragma unroll
            for (int c = 0; c < 4; c++) acc[a][b][c] = 0.f;

    for (int kt = 0; kt < NKT; kt++) {
        __syncthreads();
        {
            #pragma unroll
            for (int q = 0; q < 4; q++) {
                int c = tid + q * 256;
                int row = c >> 3, ch = c & 7;
                uint4 v = *(const uint4*)&A[(size_t)(r0 + row) * K + kt * BK + ch * 8];
                *(uint4*)&a_s[row * ASTR + ch * 8] = v;
            }
        }
        {
            #pragma unroll
            for (int q = 0; q < NC / 32; q++) {
                int c = tid + q * 256;
                int row = c / (NC / 8), ch = c % (NC / 8);
                uint4 v = *(const uint4*)&Bm[(size_t)(kt * BK + row) * NC + ch * 8];
                *(uint4*)&b_s[row * BSTR + ch * 8] = v;
            }
        }
        __syncthreads();
        #pragma unroll
        for (int k16 = 0; k16 < BK / 16; k16++) {
            unsigned afr[2][4];
            #pragma unroll
            for (int mi = 0; mi < 2; mi++)
                ldsm4(afr[mi], a32 +
                      ((wm + mi * 16 + (lane & 15)) * ASTR +
                       k16 * 16 + (lane >> 4) * 8) * 2);
            #pragma unroll
            for (int nj = 0; nj < N16; nj++) {
                unsigned bfr[4];
                ldsm4t(bfr, b32 +
                       ((k16 * 16 + (lane & 15)) * BSTR +
                        wn + nj * 16 + (lane >> 4) * 8) * 2);
                #pragma unroll
                for (int mi = 0; mi < 2; mi++) {
                    mma16816(acc[mi][2 * nj],     afr[mi], bfr[0], bfr[1]);
                    mma16816(acc[mi][2 * nj + 1], afr[mi], bfr[2], bfr[3]);
                }
            }
        }
    }

    const int g = lane >> 2, tig = lane & 3;
    #pragma unroll
    for (int mi = 0; mi < 2; mi++) {
        int rr0 = r0 + wm + mi * 16 + g;
        #pragma unroll
        for (int f = 0; f < 2 * N16; f++) {
            int col = wn + f * 8 + tig * 2;
            size_t i0 = (size_t)rr0 * NC + col;
            size_t i1 = (size_t)(rr0 + 8) * NC + col;
            *(float2*)&C[i0] = make_float2(acc[mi][f][0], acc[mi][f][1]);
            *(float2*)&C[i1] = make_float2(acc[mi][f][2], acc[mi][f][3]);
            *(__half2*)&Ch[i0] = __floats2half2_rn(acc[mi][f][0], acc[mi][f][1]);
            *(__half2*)&Ch[i1] = __floats2half2_rn(acc[mi][f][2], acc[mi][f][3]);
        }
    }
}

// ---------------- src/dst projections (+ fused atomic max of dst) -----------
template<int F, int LAYER>
__global__ void srcdst_kernel(const float* __restrict__ a_src,
                              const float* __restrict__ a_dst) {
    const float* Hm = (LAYER == 1) ? g_h1 : g_h2;
    float* so  = (LAYER == 1) ? g_src1 : g_src2;
    float* dso = (LAYER == 1) ? g_dst1 : g_dst2;
    int gw   = (blockIdx.x * blockDim.x + threadIdx.x) >> 5;
    int lane = threadIdx.x & 31;
    int hh = gw / GN;
    const float* row = Hm + (size_t)gw * F;
    float s = 0.f, d = 0.f;
    for (int c = lane; c < F; c += 32) {
        float v = row[c];
        s += v * a_src[hh * F + c];
        d += v * a_dst[hh * F + c];
    }
    for (int o = 16; o; o >>= 1) {
        s += __shfl_xor_sync(0xffffffffu, s, o);
        d += __shfl_xor_sync(0xffffffffu, d, o);
    }
    if (lane == 0) {
        so[gw] = s; dso[gw] = d;
        atomicMax(((unsigned*)g_mdst) + ((LAYER == 1) ? hh : NH), f2ord(d));
    }
}

// ---------------- fused masked-softmax attention (HMMA, half2 register-P) ---
// p = adj * max(esA_i*edA_j, esB_i*edB_j), factors in [0,1] (fp16-safe).
// Double-buffered pipeline: H tile via cp.async + {exp pairs, adjacency}
// staged for tile jt+1 during tile jt's MMA phase. Denominators via a
// ones-B MMA per k16 (exact fp32 sum of the same fp16 p as the numerator).
template<int BM, int NB, int LAYER, int JSPLIT>
__global__ __launch_bounds__(256, 2) void attn_mma_kernel(float* __restrict__ dout) {
    constexpr int KT  = 128;
    constexpr int NTS = (GN / KT) / JSPLIT;
    constexpr int WM  = BM / 4;            // 16
    constexpr int WN  = NB / 2;            // 64 or 32
    constexpr int N16 = WN / 16;           // 4 or 2
    constexpr int HSTR = NB + 8;
    constexpr int HBY  = KT * HSTR * 2;
    constexpr unsigned ONES2 = 0x3C003C00u;

    extern __shared__ __align__(16) char smem_c[];
    float*    dpart_s = (float*)smem_c;                  // [64]
    float*    inv_s   = (float*)(smem_c + 256);          // [64]
    unsigned* lut_s   = (unsigned*)(smem_c + 512);       // [4]
    uint2*    edp0    = (uint2*)(smem_c + 640);          // [64] buf0
    uint2*    edp1    = (uint2*)(smem_c + 1152);         // [64] buf1
    unsigned* adj0    = (unsigned*)(smem_c + 1664);      // [256] buf0
    unsigned* adj1    = (unsigned*)(smem_c + 2688);      // [256] buf1
    const unsigned hb0 = s2u(smem_c) + 3712;
    const unsigned hb1 = hb0 + HBY;

    const int tid = threadIdx.x;
    const int h   = blockIdx.y;
    const int i0  = blockIdx.x * BM;
    const int js  = (JSPLIT > 1) ? blockIdx.z : 0;
    const int jt_end = (js + 1) * NTS;

    const float* srcv = (LAYER == 1) ? (g_src1 + (size_t)h * GN) : g_src2;
    const float* dstv = (LAYER == 1) ? (g_dst1 + (size_t)h * GN) : g_dst2;
    const __half* Hh  = (LAYER == 1) ? (g_h1h + (size_t)h * GN * FH) : g_h2h;
    const float md = ord2f(((unsigned*)g_mdst)[(LAYER == 1) ? h : NH]);

    if (tid < 4)
        lut_s[tid] = ((tid & 1) ? 0x0000FFFFu : 0u) | ((tid & 2) ? 0xFFFF0000u : 0u);

    const int w = tid >> 5, lane = tid & 31;
    const int g = lane >> 2, tig = lane & 3;
    const int wm = (w & 3) * WM;
    const int wn = (w >> 2) * WN;

    // per-row factors (rows wm+g and wm+g+8), all <= 1
    const float s0 = srcv[i0 + wm + g];
    const float s1 = srcv[i0 + wm + g + 8];
    float t0 = s0 + md; float m0 = (t0 > 0.f) ? t0 : (ALPHA * t0);
    float t1 = s1 + md; float m1 = (t1 > 0.f) ? t1 : (ALPHA * t1);
    const __half2 esA0 = __float2half2_rn(__expf(t0 - m0));
    const __half2 esB0 = __float2half2_rn(__expf(0.2f * t0 - m0));
    const __half2 esA1 = __float2half2_rn(__expf(t1 - m1));
    const __half2 esB1 = __float2half2_rn(__expf(0.2f * t1 - m1));

    float acc[2 * N16][4];
    #pragma unroll
    for (int b = 0; b < 2 * N16; b++)
        #pragma unroll
        for (int c = 0; c < 4; c++) acc[b][c] = 0.f;
    float accd[4] = {0.f, 0.f, 0.f, 0.f};

#define STG_H(jt, hdst)                                                       \
    do {                                                                      \
        _Pragma("unroll")                                                     \
        for (int q = 0; q < KT * NB / 8 / 256; q++) {                         \
            int c_ = tid + q * 256;                                           \
            int row_ = c_ / (NB / 8), ch_ = c_ % (NB / 8);                    \
            CP_ASYNC16((hdst) + row_ * (HSTR * 2) + ch_ * 16,                 \
                       Hh + (size_t)((jt) * KT + row_) * NB + ch_ * 8);       \
        }                                                                     \
    } while (0)

#define STG_EA(jt, ebuf, abuf)                                                \
    do {                                                                      \
        if (tid < KT / 2) {                                                   \
            float d0_ = __ldg(dstv + (jt) * KT + 2 * tid)     - md;           \
            float d1_ = __ldg(dstv + (jt) * KT + 2 * tid + 1) - md;           \
            __half2 ea_ = __floats2half2_rn(__expf(d0_), __expf(d1_));        \
            __half2 eb_ = __floats2half2_rn(__expf(0.2f * d0_),               \
                                            __expf(0.2f * d1_));              \
            uint2 e_;                                                         \
            e_.x = *(unsigned*)&ea_;                                          \
            e_.y = *(unsigned*)&eb_;                                          \
            (ebuf)[tid] = e_;                                                 \
        }                                                                     \
        {                                                                     \
            int rr_ = tid >> 2, ww_ = tid & 3;                                \
            (abuf)[tid] = __ldg(g_adj + (size_t)(i0 + rr_) * (GN / 32)        \
                                + (jt) * 4 + ww_);                            \
        }                                                                     \
    } while (0)

    STG_H(js * NTS, hb0);
    CP_COMMIT();
    STG_EA(js * NTS, edp0, adj0);

    for (int jt = js * NTS; jt < jt_end; jt++) {
        const int cur = jt & 1;
        const unsigned hbc = cur ? hb1 : hb0;
        if (jt + 1 < jt_end) {
            STG_H(jt + 1, cur ? hb0 : hb1);
            CP_COMMIT();
            STG_EA(jt + 1, cur ? edp0 : edp1, cur ? adj0 : adj1);
            CP_WAIT(1);
        } else {
            CP_WAIT(0);
        }
        __syncthreads();                     // tile jt fully staged, visible
        const uint2*    edpc = cur ? edp1 : edp0;
        const unsigned* adjc = cur ? adj1 : adj0;

        #pragma unroll
        for (int k16 = 0; k16 < KT / 16; k16++) {
            const int kw = k16 >> 1;
            const int sh = (k16 & 1) * 16;
            unsigned aw0 = adjc[(wm + g) * 4 + kw];
            unsigned aw1 = adjc[(wm + g + 8) * 4 + kw];
            uint2 elo = edpc[k16 * 8 + tig];
            uint2 ehi = edpc[k16 * 8 + 4 + tig];
            __half2 eAlo = *(__half2*)&elo.x, eBlo = *(__half2*)&elo.y;
            __half2 eAhi = *(__half2*)&ehi.x, eBhi = *(__half2*)&ehi.y;
            const int b0 = sh + tig * 2, b2 = sh + 8 + tig * 2;
            __half2 p0lo = __hmax2(__hmul2(esA0, eAlo), __hmul2(esB0, eBlo));
            __half2 p1lo = __hmax2(__hmul2(esA1, eAlo), __hmul2(esB1, eBlo));
            __half2 p0hi = __hmax2(__hmul2(esA0, eAhi), __hmul2(esB0, eBhi));
            __half2 p1hi = __hmax2(__hmul2(esA1, eAhi), __hmul2(esB1, eBhi));
            unsigned afr[4];
            afr[0] = (*(unsigned*)&p0lo) & lut_s[(aw0 >> b0) & 3u];
            afr[1] = (*(unsigned*)&p1lo) & lut_s[(aw1 >> b0) & 3u];
            afr[2] = (*(unsigned*)&p0hi) & lut_s[(aw0 >> b2) & 3u];
            afr[3] = (*(unsigned*)&p1hi) & lut_s[(aw1 >> b2) & 3u];
            if (w < 4) mma16816(accd, afr, ONES2, ONES2);   // row sums (denom)
            #pragma unroll
            for (int nj = 0; nj < N16; nj++) {
                unsigned bfr[4];
                ldsm4t(bfr, hbc +
                       ((k16 * 16 + (lane & 15)) * HSTR +
                        wn + nj * 16 + (lane >> 4) * 8) * 2);
                mma16816(acc[2 * nj],     afr, bfr[0], bfr[1]);
                mma16816(acc[2 * nj + 1], afr, bfr[2], bfr[3]);
            }
        }
        __syncthreads();                     // done with buf cur before reuse
    }
#undef STG_H
#undef STG_EA

    // denominators: accd[0]=row wm+g, accd[2]=row wm+g+8 (all tig identical)
    if (w < 4 && tig == 0) {
        dpart_s[wm + g]     = accd[0];
        dpart_s[wm + g + 8] = accd[2];
    }
    __syncthreads();
    if (tid < BM) {
        if (LAYER == 1) inv_s[tid] = 1.f / dpart_s[tid];
        else            PDEN[js * GN + i0 + tid] = dpart_s[tid];
    }
    __syncthreads();

    if (LAYER == 1) {
        int rr0 = wm + g;
        float inv0 = inv_s[rr0], inv1 = inv_s[rr0 + 8];
        #pragma unroll
        for (int f = 0; f < 2 * N16; f++) {
            int col = wn + f * 8 + tig * 2;
            float v0 = acc[f][0] * inv0;
            float v1 = acc[f][1] * inv0;
            float v2 = acc[f][2] * inv1;
            float v3 = acc[f][3] * inv1;
            v0 = (v0 > 0.f) ? v0 : expm1f(v0);
            v1 = (v1 > 0.f) ? v1 : expm1f(v1);
            v2 = (v2 > 0.f) ? v2 : expm1f(v2);
            v3 = (v3 > 0.f) ? v3 : expm1f(v3);
            size_t o0 = (size_t)(i0 + rr0) * (NH * FH) + h * FH + col;
            size_t o1 = (size_t)(i0 + rr0 + 8) * (NH * FH) + h * FH + col;
            *(__half2*)&X2H[o0] = __floats2half2_rn(v0, v1);
            *(__half2*)&X2H[o1] = __floats2half2_rn(v2, v3);
        }
    } else {
        int rr0 = wm + g;
        #pragma unroll
        for (int f = 0; f < 2 * N16; f++) {
            int col = wn + f * 8 + tig * 2;
            float* o0 = PNUM + (size_t)js * GN * FOUT + (size_t)(i0 + rr0) * FOUT + col;
            float* o1 = PNUM + (size_t)js * GN * FOUT + (size_t)(i0 + rr0 + 8) * FOUT + col;
            *(float2*)o0 = make_float2(acc[f][0], acc[f][1]);
            *(float2*)o1 = make_float2(acc[f][2], acc[f][3]);
        }
    }
}

// ---------------- combine: sum partials, normalize, ELU, log_softmax --------
__global__ void combine_kernel(float* __restrict__ out) {
    int gw   = (blockIdx.x * blockDim.x + threadIdx.x) >> 5;   // row
    int lane = threadIdx.x & 31;
    float den = 0.f;
    #pragma unroll
    for (int js = 0; js < 4; js++) den += PDEN[js * GN + gw];
    float inv = 1.f / den;
    float v0 = 0.f, v1 = 0.f;
    #pragma unroll
    for (int js = 0; js < 4; js++) {
        const float* p = PNUM + (size_t)js * GN * FOUT + (size_t)gw * FOUT;
        v0 += p[lane];
        v1 += p[lane + 32];
    }
    v0 *= inv; v1 *= inv;
    v0 = (v0 > 0.f) ? v0 : expm1f(v0);
    v1 = (v1 > 0.f) ? v1 : expm1f(v1);
    float m = fmaxf(v0, v1);
    #pragma unroll
    for (int o = 16; o; o >>= 1) m = fmaxf(m, __shfl_xor_sync(0xffffffffu, m, o));
    float s = __expf(v0 - m) + __expf(v1 - m);
    #pragma unroll
    for (int o = 16; o; o >>= 1) s += __shfl_xor_sync(0xffffffffu, s, o);
    float lse = m + logf(s);
    out[(size_t)gw * FOUT + lane]      = v0 - lse;
    out[(size_t)gw * FOUT + lane + 32] = v1 - lse;
}

// ---------------- launch ----------------------------------------------------
extern "C" void kernel_launch(void* const* d_in, const int* in_sizes, int n_in,
                              void* d_out, int out_size) {
    const float* features = (const float*)d_in[0];
    const int*   adj      = (const int*)d_in[1];
    const float* W1  = (const float*)d_in[2];
    const float* a1s = (const float*)d_in[3];
    const float* a1d = (const float*)d_in[4];
    const float* W2  = (const float*)d_in[5];
    const float* a2s = (const float*)d_in[6];
    const float* a2d = (const float*)d_in[7];
    float* out = (float*)d_out;

    const int SMEM1 = 3712 + 2 * 128 * 136 * 2;   // 73344
    const int SMEM2 = 3712 + 2 * 128 * 72 * 2;    // 40576
    cudaFuncSetAttribute(attn_mma_kernel<64, FH, 1, 1>,
                         cudaFuncAttributeMaxDynamicSharedMemorySize, SMEM1);
    cudaFuncSetAttribute(attn_mma_kernel<64, FOUT, 2, 4>,
                         cudaFuncAttributeMaxDynamicSharedMemorySize, SMEM2);

    pack_adj_kernel<<<(GN * GN) / 256, 256>>>(adj, features, W1, W2);

    // layer 1
    hgemm_kernel<FIN, FH, 1><<<dim3(GN / 128, 1, NH), 256>>>();
    srcdst_kernel<FH, 1><<<(NH * GN) / 8, 256>>>(a1s, a1d);
    attn_mma_kernel<64, FH, 1, 1><<<dim3(GN / 64, NH, 1), 256, SMEM1>>>(nullptr);

    // layer 2
    hgemm_kernel<NH * FH, FOUT, 2><<<dim3(GN / 128, 1, 1), 256>>>();
    srcdst_kernel<FOUT, 2><<<GN / 8, 256>>>(a2s, a2d);
    attn_mma_kernel<64, FOUT, 2, 4><<<dim3(GN / 64, 1, 4), 256, SMEM2>>>(nullptr);
    combine_kernel<<<GN / 8, 256>>>(out);
}